// round 1
// baseline (speedup 1.0000x reference)
#include <cuda_runtime.h>

// Problem constants (fixed shapes for this problem instance)
#define NN   100000
#define EE   3200000
#define INCH 256
#define HID  128
#define OUTC 64

// Scratch (allocation-free rule: __device__ globals)
__device__ float g_B1[(size_t)NN * HID];   // x@W1, then H (post-relu)
__device__ float g_B2[(size_t)NN * HID];   // aggregation target
__device__ float g_dinv[NN];               // deg -> rsqrt(deg)
__device__ int   g_idx64;                  // 1 if edge_index is int64, 0 if int32

// ---------------------------------------------------------------------------
// dtype detection: if edge_index is int64 (little-endian), every odd int32
// word is the high half of a node id < 100000 => 0. With genuine int32 data,
// 4096 random ids in [0,100000) being all zero is impossible.
// ---------------------------------------------------------------------------
__global__ void k_detect(const int* __restrict__ ei32) {
    __shared__ int nz;
    if (threadIdx.x == 0) nz = 0;
    __syncthreads();
    int local = 0;
    for (int i = threadIdx.x; i < 4096; i += blockDim.x)
        if (ei32[2 * i + 1] != 0) local = 1;
    if (local) atomicOr(&nz, 1);
    __syncthreads();
    if (threadIdx.x == 0) g_idx64 = (nz == 0) ? 1 : 0;
}

__device__ __forceinline__ int load_idx(const void* ei, long long pos) {
    if (g_idx64) return (int)((const long long*)ei)[pos];
    return ((const int*)ei)[pos];
}

// ---------------------------------------------------------------------------
// Degree / normalization
// ---------------------------------------------------------------------------
__global__ void k_init_deg() {
    int i = blockIdx.x * blockDim.x + threadIdx.x;
    if (i < NN) g_dinv[i] = 1.0f;   // self-loop
}

__global__ void k_deg(const void* __restrict__ ei, int e) {
    int i = blockIdx.x * blockDim.x + threadIdx.x;
    if (i < e) {
        int d = load_idx(ei, (long long)e + i);   // dst row
        atomicAdd(&g_dinv[d], 1.0f);
    }
}

__global__ void k_rsqrt() {
    int i = blockIdx.x * blockDim.x + threadIdx.x;
    if (i < NN) g_dinv[i] = rsqrtf(g_dinv[i]);
}

__global__ void k_zeroB2() {
    int i = blockIdx.x * blockDim.x + threadIdx.x;
    if (i < NN * (HID / 4))
        reinterpret_cast<float4*>(g_B2)[i] = make_float4(0.f, 0.f, 0.f, 0.f);
}

// ---------------------------------------------------------------------------
// GEMM1: g_B1 = X[NN,256] @ W1[256,128]   (no bias; bias fused in epilogue1)
// Tile 64x128, KT=16, 256 threads, micro-tile 4x8 per thread.
// ---------------------------------------------------------------------------
#define TM 64
#define KT 16

__global__ __launch_bounds__(256) void k_gemm1(const float* __restrict__ X,
                                               const float* __restrict__ W) {
    __shared__ float As[TM][KT + 1];
    __shared__ float Bs[KT][HID];
    int row0 = blockIdx.x * TM;
    int t  = threadIdx.x;
    int ty = t >> 4;        // 0..15 (row group of 4)
    int tx = t & 15;        // 0..15 (col group of 8)

    float acc[4][8];
#pragma unroll
    for (int r = 0; r < 4; r++)
#pragma unroll
        for (int c = 0; c < 8; c++) acc[r][c] = 0.f;

    for (int k0 = 0; k0 < INCH; k0 += KT) {
        {   // stage A tile 64x16 (transposed scatter, padded to kill conflicts)
            int row = t >> 2;
            int kk  = (t & 3) * 4;
            int gr  = row0 + row;
            float4 v = make_float4(0.f, 0.f, 0.f, 0.f);
            if (gr < NN)
                v = *reinterpret_cast<const float4*>(X + (long long)gr * INCH + k0 + kk);
            As[row][kk]     = v.x;
            As[row][kk + 1] = v.y;
            As[row][kk + 2] = v.z;
            As[row][kk + 3] = v.w;
        }
        {   // stage B tile 16x128
            int idx = t * 8;
            int kk  = idx >> 7;
            int c   = idx & 127;
            const float* src = W + (long long)(k0 + kk) * HID + c;
            *reinterpret_cast<float4*>(&Bs[kk][c])     = *reinterpret_cast<const float4*>(src);
            *reinterpret_cast<float4*>(&Bs[kk][c + 4]) = *reinterpret_cast<const float4*>(src + 4);
        }
        __syncthreads();
#pragma unroll
        for (int kk = 0; kk < KT; kk++) {
            float a[4];
#pragma unroll
            for (int r = 0; r < 4; r++) a[r] = As[ty * 4 + r][kk];
            float4 b0 = *reinterpret_cast<const float4*>(&Bs[kk][tx * 8]);
            float4 b1 = *reinterpret_cast<const float4*>(&Bs[kk][tx * 8 + 4]);
            float b[8] = {b0.x, b0.y, b0.z, b0.w, b1.x, b1.y, b1.z, b1.w};
#pragma unroll
            for (int r = 0; r < 4; r++)
#pragma unroll
                for (int c = 0; c < 8; c++) acc[r][c] = fmaf(a[r], b[c], acc[r][c]);
        }
        __syncthreads();
    }
#pragma unroll
    for (int r = 0; r < 4; r++) {
        int gr = row0 + ty * 4 + r;
        if (gr < NN) {
            float4 v0 = make_float4(acc[r][0], acc[r][1], acc[r][2], acc[r][3]);
            float4 v1 = make_float4(acc[r][4], acc[r][5], acc[r][6], acc[r][7]);
            float* dst = g_B1 + (long long)gr * HID + tx * 8;
            *reinterpret_cast<float4*>(dst)     = v0;
            *reinterpret_cast<float4*>(dst + 4) = v1;
        }
    }
}

// ---------------------------------------------------------------------------
// Edge propagation: one warp per edge. Gather 128 floats of g_B1[src],
// scale by dinv[src]*dinv[dst], vectorized float4 RED into g_B2[dst].
// ---------------------------------------------------------------------------
__global__ __launch_bounds__(256) void k_prop(const void* __restrict__ ei, int e) {
    int w    = (int)((blockIdx.x * (long long)blockDim.x + threadIdx.x) >> 5);
    int lane = threadIdx.x & 31;
    if (w >= e) return;
    int s = 0, d = 0;
    float n = 0.f;
    if (lane == 0) {
        s = load_idx(ei, w);
        d = load_idx(ei, (long long)e + w);
        n = g_dinv[s] * g_dinv[d];
    }
    s = __shfl_sync(0xffffffffu, s, 0);
    d = __shfl_sync(0xffffffffu, d, 0);
    n = __shfl_sync(0xffffffffu, n, 0);

    float4 v = reinterpret_cast<const float4*>(g_B1 + (long long)s * HID)[lane];
    v.x *= n; v.y *= n; v.z *= n; v.w *= n;
    atomicAdd(reinterpret_cast<float4*>(g_B2 + (long long)d * HID) + lane, v);
}

// ---------------------------------------------------------------------------
// Epilogue 1: H = relu(agg + self_loop + b1), written back into g_B1
// ---------------------------------------------------------------------------
__global__ void k_epi1(const float* __restrict__ b1) {
    int i = blockIdx.x * blockDim.x + threadIdx.x;
    if (i >= NN * (HID / 4)) return;
    int node = i >> 5;              // /32 float4-chunks per row
    int c4   = i & 31;
    float di = g_dinv[node];
    float sl = di * di;
    float4 h  = reinterpret_cast<const float4*>(g_B1)[i];
    float4 a  = reinterpret_cast<const float4*>(g_B2)[i];
    float4 bb = reinterpret_cast<const float4*>(b1)[c4];
    float4 r;
    r.x = fmaxf(fmaf(h.x, sl, a.x) + bb.x, 0.f);
    r.y = fmaxf(fmaf(h.y, sl, a.y) + bb.y, 0.f);
    r.z = fmaxf(fmaf(h.z, sl, a.z) + bb.z, 0.f);
    r.w = fmaxf(fmaf(h.w, sl, a.w) + bb.w, 0.f);
    reinterpret_cast<float4*>(g_B1)[i] = r;
}

// Epilogue 2: g = agg + self_loop (no bias/relu), written into g_B2
__global__ void k_epi2() {
    int i = blockIdx.x * blockDim.x + threadIdx.x;
    if (i >= NN * (HID / 4)) return;
    int node = i >> 5;
    float di = g_dinv[node];
    float sl = di * di;
    float4 h = reinterpret_cast<const float4*>(g_B1)[i];
    float4 a = reinterpret_cast<const float4*>(g_B2)[i];
    a.x = fmaf(h.x, sl, a.x);
    a.y = fmaf(h.y, sl, a.y);
    a.z = fmaf(h.z, sl, a.z);
    a.w = fmaf(h.w, sl, a.w);
    reinterpret_cast<float4*>(g_B2)[i] = a;
}

// ---------------------------------------------------------------------------
// GEMM2 (dual output): [mu | ls] = g_B2[NN,128] @ [Wmu | Wls][128,64+64] + bias
// mu -> out[0 : NN*64], ls -> out[NN*64 : 2*NN*64]
// ---------------------------------------------------------------------------
__global__ __launch_bounds__(256) void k_gemm2(const float* __restrict__ Wmu,
                                               const float* __restrict__ bmu,
                                               const float* __restrict__ Wls,
                                               const float* __restrict__ bls,
                                               float* __restrict__ out) {
    __shared__ float As[TM][KT + 1];
    __shared__ float Bs[KT][HID];
    int row0 = blockIdx.x * TM;
    int t  = threadIdx.x;
    int ty = t >> 4;
    int tx = t & 15;

    float acc[4][8];
#pragma unroll
    for (int r = 0; r < 4; r++)
#pragma unroll
        for (int c = 0; c < 8; c++) acc[r][c] = 0.f;

    for (int k0 = 0; k0 < HID; k0 += KT) {
        {
            int row = t >> 2;
            int kk  = (t & 3) * 4;
            int gr  = row0 + row;
            float4 v = make_float4(0.f, 0.f, 0.f, 0.f);
            if (gr < NN)
                v = *reinterpret_cast<const float4*>(g_B2 + (long long)gr * HID + k0 + kk);
            As[row][kk]     = v.x;
            As[row][kk + 1] = v.y;
            As[row][kk + 2] = v.z;
            As[row][kk + 3] = v.w;
        }
        {
            int idx = t * 8;
            int kk  = idx >> 7;
            int c   = idx & 127;
            const float* src = (c < 64) ? (Wmu + (long long)(k0 + kk) * OUTC + c)
                                        : (Wls + (long long)(k0 + kk) * OUTC + (c - 64));
            *reinterpret_cast<float4*>(&Bs[kk][c])     = *reinterpret_cast<const float4*>(src);
            *reinterpret_cast<float4*>(&Bs[kk][c + 4]) = *reinterpret_cast<const float4*>(src + 4);
        }
        __syncthreads();
#pragma unroll
        for (int kk = 0; kk < KT; kk++) {
            float a[4];
#pragma unroll
            for (int r = 0; r < 4; r++) a[r] = As[ty * 4 + r][kk];
            float4 b0 = *reinterpret_cast<const float4*>(&Bs[kk][tx * 8]);
            float4 b1 = *reinterpret_cast<const float4*>(&Bs[kk][tx * 8 + 4]);
            float b[8] = {b0.x, b0.y, b0.z, b0.w, b1.x, b1.y, b1.z, b1.w};
#pragma unroll
            for (int r = 0; r < 4; r++)
#pragma unroll
                for (int c = 0; c < 8; c++) acc[r][c] = fmaf(a[r], b[c], acc[r][c]);
        }
        __syncthreads();
    }

    int col0  = tx * 8;
    bool isMu = (col0 < 64);
    int  c0   = isMu ? col0 : (col0 - 64);
    const float* bias = isMu ? bmu : bls;
    float*       base = isMu ? out : (out + (long long)NN * OUTC);
    float4 bv0 = *reinterpret_cast<const float4*>(bias + c0);
    float4 bv1 = *reinterpret_cast<const float4*>(bias + c0 + 4);

#pragma unroll
    for (int r = 0; r < 4; r++) {
        int gr = row0 + ty * 4 + r;
        if (gr < NN) {
            float4 v0 = make_float4(acc[r][0] + bv0.x, acc[r][1] + bv0.y,
                                    acc[r][2] + bv0.z, acc[r][3] + bv0.w);
            float4 v1 = make_float4(acc[r][4] + bv1.x, acc[r][5] + bv1.y,
                                    acc[r][6] + bv1.z, acc[r][7] + bv1.w);
            float* dst = base + (long long)gr * OUTC + c0;
            *reinterpret_cast<float4*>(dst)     = v0;
            *reinterpret_cast<float4*>(dst + 4) = v1;
        }
    }
}

// ---------------------------------------------------------------------------
extern "C" void kernel_launch(void* const* d_in, const int* in_sizes, int n_in,
                              void* d_out, int out_size) {
    const float* x   = (const float*)d_in[0];
    const void*  ei  = d_in[1];
    const float* W1  = (const float*)d_in[2];
    const float* b1  = (const float*)d_in[3];
    const float* Wmu = (const float*)d_in[4];
    const float* bmu = (const float*)d_in[5];
    const float* Wls = (const float*)d_in[6];
    const float* bls = (const float*)d_in[7];
    float* out = (float*)d_out;

    const int E = in_sizes[1] / 2;   // element count / 2 rows

    const int nThr    = 256;
    const int nodeBlk = (NN + nThr - 1) / nThr;
    const int vecBlk  = (NN * (HID / 4) + nThr - 1) / nThr;
    const int edgeBlk = (E + nThr - 1) / nThr;
    const int propBlk = (int)(((long long)E * 32 + nThr - 1) / nThr);
    const int gemmBlk = (NN + TM - 1) / TM;

    // 0. dtype detection (int32 vs int64 edge_index)
    k_detect<<<1, 256>>>((const int*)ei);

    // 1. degree + rsqrt
    k_init_deg<<<nodeBlk, nThr>>>();
    k_deg<<<edgeBlk, nThr>>>(ei, E);
    k_rsqrt<<<nodeBlk, nThr>>>();

    // 2. layer 1: GEMM -> propagate -> bias+relu
    k_gemm1<<<gemmBlk, nThr>>>(x, W1);
    k_zeroB2<<<vecBlk, nThr>>>();
    k_prop<<<propBlk, nThr>>>(ei, E);
    k_epi1<<<vecBlk, nThr>>>(b1);

    // 3. shared propagation for mu/logstd (A is linear: A(h@W) = (A h)@W)
    k_zeroB2<<<vecBlk, nThr>>>();
    k_prop<<<propBlk, nThr>>>(ei, E);
    k_epi2<<<vecBlk, nThr>>>();

    // 4. dual output GEMM with bias
    k_gemm2<<<gemmBlk, nThr>>>(Wmu, bmu, Wls, bls, out);
}

// round 4
// speedup vs baseline: 1.6512x; 1.6512x over previous
#include <cuda_runtime.h>

#define NN    100000
#define EEMAX 4000000
#define INCH  256
#define HID   128
#define OUTC  64
#define FULLMASK 0xffffffffu

// -------- scratch (device globals; referenced ONLY from device code) --------
__device__ float g_B1[(size_t)NN * HID];
__device__ float g_B2[(size_t)NN * HID];
__device__ float g_dinv[NN];
__device__ int   g_deg[NN];
__device__ int   g_rowptr[NN + 1];
__device__ int   g_cursor[NN];
__device__ int   g_csr[EEMAX];
__device__ int   g_idx64;

// ---------------------------------------------------------------------------
// edge_index dtype detection (int64 vs int32): for int64 little-endian, every
// odd 32-bit word is the high half of an id < 100000 => 0.
// ---------------------------------------------------------------------------
__global__ void k_detect(const int* __restrict__ ei32) {
    __shared__ int nz;
    if (threadIdx.x == 0) nz = 0;
    __syncthreads();
    int local = 0;
    for (int i = threadIdx.x; i < 4096; i += blockDim.x)
        if (ei32[2 * i + 1] != 0) local = 1;
    if (local) atomicOr(&nz, 1);
    __syncthreads();
    if (threadIdx.x == 0) g_idx64 = (nz == 0) ? 1 : 0;
}

__device__ __forceinline__ int load_idx(const void* ei, long long pos) {
    if (g_idx64) return (int)((const long long*)ei)[pos];
    return ((const int*)ei)[pos];
}

// ---------------------------------------------------------------------------
// CSR construction
// ---------------------------------------------------------------------------
__global__ void k_zero_deg() {
    int i = blockIdx.x * blockDim.x + threadIdx.x;
    if (i < NN) g_deg[i] = 0;
}

__global__ void k_deg(const void* __restrict__ ei, int e) {
    int i = blockIdx.x * blockDim.x + threadIdx.x;
    if (i < e) atomicAdd(&g_deg[load_idx(ei, (long long)e + i)], 1);
}

// Single-block scan: rowptr = exclusive scan of deg; also cursor and dinv.
__global__ __launch_bounds__(1024) void k_scan_build(int n, int e) {
    __shared__ int totals[1024];
    int t = threadIdx.x;
    const int CH = (n + 1023) / 1024;          // 98
    int lo = t * CH;
    int hi = lo + CH; if (hi > n) hi = n;
    if (lo > n) lo = n;

    int s = 0;
    for (int i = lo; i < hi; i++) s += g_deg[i];
    totals[t] = s;
    __syncthreads();

    for (int off = 1; off < 1024; off <<= 1) {
        int v = 0;
        if (t >= off) v = totals[t - off];
        __syncthreads();
        totals[t] += v;
        __syncthreads();
    }

    int ex = totals[t] - s;                    // exclusive prefix of this chunk
    for (int i = lo; i < hi; i++) {
        g_rowptr[i] = ex;
        g_cursor[i] = ex;
        g_dinv[i]   = rsqrtf((float)g_deg[i] + 1.0f);
        ex += g_deg[i];
    }
    if (t == 0) g_rowptr[n] = e;
}

__global__ void k_scatter(const void* __restrict__ ei, int e) {
    int i = blockIdx.x * blockDim.x + threadIdx.x;
    if (i < e) {
        int s = load_idx(ei, i);
        int d = load_idx(ei, (long long)e + i);
        int pos = atomicAdd(&g_cursor[d], 1);
        g_csr[pos] = s;
    }
}

// ---------------------------------------------------------------------------
// GEMM1 (round-1 structure, known-correct): g_B1 = (X @ W1) * dinv[row]
// ---------------------------------------------------------------------------
#define TM 64
#define KT 16

__global__ __launch_bounds__(256) void k_gemm1(const float* __restrict__ X,
                                               const float* __restrict__ W) {
    __shared__ float As[TM][KT + 1];
    __shared__ float Bs[KT][HID];
    int row0 = blockIdx.x * TM;
    int t  = threadIdx.x;
    int ty = t >> 4;
    int tx = t & 15;

    float acc[4][8];
#pragma unroll
    for (int r = 0; r < 4; r++)
#pragma unroll
        for (int c = 0; c < 8; c++) acc[r][c] = 0.f;

    for (int k0 = 0; k0 < INCH; k0 += KT) {
        {
            int row = t >> 2;
            int kk  = (t & 3) * 4;
            int gr  = row0 + row;
            float4 v = make_float4(0.f, 0.f, 0.f, 0.f);
            if (gr < NN)
                v = *reinterpret_cast<const float4*>(X + (long long)gr * INCH + k0 + kk);
            As[row][kk]     = v.x;
            As[row][kk + 1] = v.y;
            As[row][kk + 2] = v.z;
            As[row][kk + 3] = v.w;
        }
        {
            int idx = t * 8;
            int kk  = idx >> 7;
            int c   = idx & 127;
            const float* src = W + (long long)(k0 + kk) * HID + c;
            *reinterpret_cast<float4*>(&Bs[kk][c])     = *reinterpret_cast<const float4*>(src);
            *reinterpret_cast<float4*>(&Bs[kk][c + 4]) = *reinterpret_cast<const float4*>(src + 4);
        }
        __syncthreads();
#pragma unroll
        for (int kk = 0; kk < KT; kk++) {
            float a[4];
#pragma unroll
            for (int r = 0; r < 4; r++) a[r] = As[ty * 4 + r][kk];
            float4 b0 = *reinterpret_cast<const float4*>(&Bs[kk][tx * 8]);
            float4 b1 = *reinterpret_cast<const float4*>(&Bs[kk][tx * 8 + 4]);
            float b[8] = {b0.x, b0.y, b0.z, b0.w, b1.x, b1.y, b1.z, b1.w};
#pragma unroll
            for (int r = 0; r < 4; r++)
#pragma unroll
                for (int c = 0; c < 8; c++) acc[r][c] = fmaf(a[r], b[c], acc[r][c]);
        }
        __syncthreads();
    }
#pragma unroll
    for (int r = 0; r < 4; r++) {
        int gr = row0 + ty * 4 + r;
        if (gr < NN) {
            float s = g_dinv[gr];   // pre-scale for norm-factored propagation
            float4 v0 = make_float4(acc[r][0] * s, acc[r][1] * s, acc[r][2] * s, acc[r][3] * s);
            float4 v1 = make_float4(acc[r][4] * s, acc[r][5] * s, acc[r][6] * s, acc[r][7] * s);
            float* dst = g_B1 + (long long)gr * HID + tx * 8;
            *reinterpret_cast<float4*>(dst)     = v0;
            *reinterpret_cast<float4*>(dst + 4) = v1;
        }
    }
}

// ---------------------------------------------------------------------------
// CSR propagation, globals referenced from DEVICE code only.
// Body shared via inline function on device pointers obtained in-kernel.
// ---------------------------------------------------------------------------
__device__ __forceinline__ void prop_body(const float* __restrict__ in,
                                          float* __restrict__ outp,
                                          const float* __restrict__ bias,
                                          int mode) {
    int node = (int)((blockIdx.x * (long long)blockDim.x + threadIdx.x) >> 5);
    int lane = threadIdx.x & 31;
    if (node >= NN) return;

    const float4* IN = (const float4*)in;
    int beg = g_rowptr[node];
    int end = g_rowptr[node + 1];

    float4 acc = IN[(long long)node * 32 + lane];   // self-loop term (pre-scaled)

    int e = beg;
    for (; e + 4 <= end; e += 4) {
        int s0 = g_csr[e];
        int s1 = g_csr[e + 1];
        int s2 = g_csr[e + 2];
        int s3 = g_csr[e + 3];
        float4 v0 = IN[(long long)s0 * 32 + lane];
        float4 v1 = IN[(long long)s1 * 32 + lane];
        float4 v2 = IN[(long long)s2 * 32 + lane];
        float4 v3 = IN[(long long)s3 * 32 + lane];
        acc.x += (v0.x + v1.x) + (v2.x + v3.x);
        acc.y += (v0.y + v1.y) + (v2.y + v3.y);
        acc.z += (v0.z + v1.z) + (v2.z + v3.z);
        acc.w += (v0.w + v1.w) + (v2.w + v3.w);
    }
    for (; e < end; e++) {
        int s = g_csr[e];
        float4 v = IN[(long long)s * 32 + lane];
        acc.x += v.x; acc.y += v.y; acc.z += v.z; acc.w += v.w;
    }

    float dn = g_dinv[node];
    acc.x *= dn; acc.y *= dn; acc.z *= dn; acc.w *= dn;
    if (mode == 1) {
        float4 b = ((const float4*)bias)[lane];
        acc.x = fmaxf(acc.x + b.x, 0.f) * dn;
        acc.y = fmaxf(acc.y + b.y, 0.f) * dn;
        acc.z = fmaxf(acc.z + b.z, 0.f) * dn;
        acc.w = fmaxf(acc.w + b.w, 0.f) * dn;
    }
    ((float4*)outp)[(long long)node * 32 + lane] = acc;
}

// prop1: g_B1 -> g_B2, with bias+relu, output prescaled by dinv
__global__ __launch_bounds__(256) void k_prop1(const float* __restrict__ b1) {
    prop_body(g_B1, g_B2, b1, 1);
}

// prop2: g_B2 -> g_B1, plain aggregation (feeds gemm2)
__global__ __launch_bounds__(256) void k_prop2() {
    prop_body(g_B2, g_B1, (const float*)0, 0);
}

// ---------------------------------------------------------------------------
// GEMM2: [mu | ls] = g_B1 @ [Wmu | Wls] + bias  (g_B1 = A·H, device global)
// ---------------------------------------------------------------------------
__global__ __launch_bounds__(256) void k_gemm2(const float* __restrict__ Wmu,
                                               const float* __restrict__ bmu,
                                               const float* __restrict__ Wls,
                                               const float* __restrict__ bls,
                                               float* __restrict__ out) {
    __shared__ float As[TM][KT + 1];
    __shared__ float Bs[KT][HID];
    int row0 = blockIdx.x * TM;
    int t  = threadIdx.x;
    int ty = t >> 4;
    int tx = t & 15;

    float acc[4][8];
#pragma unroll
    for (int r = 0; r < 4; r++)
#pragma unroll
        for (int c = 0; c < 8; c++) acc[r][c] = 0.f;

    for (int k0 = 0; k0 < HID; k0 += KT) {
        {
            int row = t >> 2;
            int kk  = (t & 3) * 4;
            int gr  = row0 + row;
            float4 v = make_float4(0.f, 0.f, 0.f, 0.f);
            if (gr < NN)
                v = *reinterpret_cast<const float4*>(g_B1 + (long long)gr * HID + k0 + kk);
            As[row][kk]     = v.x;
            As[row][kk + 1] = v.y;
            As[row][kk + 2] = v.z;
            As[row][kk + 3] = v.w;
        }
        {
            int idx = t * 8;
            int kk  = idx >> 7;
            int c   = idx & 127;
            const float* src = (c < 64) ? (Wmu + (long long)(k0 + kk) * OUTC + c)
                                        : (Wls + (long long)(k0 + kk) * OUTC + (c - 64));
            *reinterpret_cast<float4*>(&Bs[kk][c])     = *reinterpret_cast<const float4*>(src);
            *reinterpret_cast<float4*>(&Bs[kk][c + 4]) = *reinterpret_cast<const float4*>(src + 4);
        }
        __syncthreads();
#pragma unroll
        for (int kk = 0; kk < KT; kk++) {
            float a[4];
#pragma unroll
            for (int r = 0; r < 4; r++) a[r] = As[ty * 4 + r][kk];
            float4 b0 = *reinterpret_cast<const float4*>(&Bs[kk][tx * 8]);
            float4 b1 = *reinterpret_cast<const float4*>(&Bs[kk][tx * 8 + 4]);
            float b[8] = {b0.x, b0.y, b0.z, b0.w, b1.x, b1.y, b1.z, b1.w};
#pragma unroll
            for (int r = 0; r < 4; r++)
#pragma unroll
                for (int c = 0; c < 8; c++) acc[r][c] = fmaf(a[r], b[c], acc[r][c]);
        }
        __syncthreads();
    }

    int col0  = tx * 8;
    bool isMu = (col0 < 64);
    int  c0   = isMu ? col0 : (col0 - 64);
    const float* bias = isMu ? bmu : bls;
    float*       base = isMu ? out : (out + (long long)NN * OUTC);
    float4 bv0 = *reinterpret_cast<const float4*>(bias + c0);
    float4 bv1 = *reinterpret_cast<const float4*>(bias + c0 + 4);

#pragma unroll
    for (int r = 0; r < 4; r++) {
        int gr = row0 + ty * 4 + r;
        if (gr < NN) {
            float4 v0 = make_float4(acc[r][0] + bv0.x, acc[r][1] + bv0.y,
                                    acc[r][2] + bv0.z, acc[r][3] + bv0.w);
            float4 v1 = make_float4(acc[r][4] + bv1.x, acc[r][5] + bv1.y,
                                    acc[r][6] + bv1.z, acc[r][7] + bv1.w);
            float* dst = base + (long long)gr * OUTC + c0;
            *reinterpret_cast<float4*>(dst)     = v0;
            *reinterpret_cast<float4*>(dst + 4) = v1;
        }
    }
}

// ---------------------------------------------------------------------------
extern "C" void kernel_launch(void* const* d_in, const int* in_sizes, int n_in,
                              void* d_out, int out_size) {
    const float* x   = (const float*)d_in[0];
    const void*  ei  = d_in[1];
    const float* W1  = (const float*)d_in[2];
    const float* b1  = (const float*)d_in[3];
    const float* Wmu = (const float*)d_in[4];
    const float* bmu = (const float*)d_in[5];
    const float* Wls = (const float*)d_in[6];
    const float* bls = (const float*)d_in[7];
    float* out = (float*)d_out;

    const int E = in_sizes[1] / 2;

    const int nThr    = 256;
    const int nodeBlk = (NN + nThr - 1) / nThr;
    const int edgeBlk = (E + nThr - 1) / nThr;
    const int propBlk = (int)(((long long)NN * 32 + nThr - 1) / nThr);
    const int gemmBlk = (NN + TM - 1) / TM;

    // dtype detection
    k_detect<<<1, 256>>>((const int*)ei);

    // CSR build + dinv
    k_zero_deg<<<nodeBlk, nThr>>>();
    k_deg<<<edgeBlk, nThr>>>(ei, E);
    k_scan_build<<<1, 1024>>>(NN, E);
    k_scatter<<<edgeBlk, nThr>>>(ei, E);

    // layer 1: GEMM (dinv-prescaled) -> prop (+bias+relu, prescaled output)
    k_gemm1<<<gemmBlk, nThr>>>(x, W1);
    k_prop1<<<propBlk, nThr>>>(b1);

    // shared propagation for mu/logstd (A linear: A(h@W) = (A h)@W)
    k_prop2<<<propBlk, nThr>>>();

    // dual output GEMM with bias
    k_gemm2<<<gemmBlk, nThr>>>(Wmu, bmu, Wls, bls, out);
}

// round 5
// speedup vs baseline: 2.2011x; 1.3330x over previous
#include <cuda_runtime.h>

#define NN    100000
#define EEMAX 4000000
#define INCH  256
#define HID   128
#define OUTC  64
#define FULLMASK 0xffffffffu

// -------- scratch (device globals; referenced ONLY from device code) --------
__device__ float g_B1[(size_t)NN * HID];
__device__ float g_B2[(size_t)NN * HID];
__device__ float g_dinv[NN];
__device__ int   g_deg[NN];
__device__ int   g_rowptr[NN + 1];
__device__ int   g_cursor[NN];
__device__ int   g_csr[EEMAX];
__device__ int   g_partial[128];
__device__ int   g_idx64;

// ---------------------------------------------------------------------------
// edge_index dtype detection (int64 vs int32): for int64 little-endian, every
// odd 32-bit word is the high half of an id < 100000 => 0.
// ---------------------------------------------------------------------------
__global__ void k_detect(const int* __restrict__ ei32) {
    __shared__ int nz;
    if (threadIdx.x == 0) nz = 0;
    __syncthreads();
    int local = 0;
    for (int i = threadIdx.x; i < 4096; i += blockDim.x)
        if (ei32[2 * i + 1] != 0) local = 1;
    if (local) atomicOr(&nz, 1);
    __syncthreads();
    if (threadIdx.x == 0) g_idx64 = (nz == 0) ? 1 : 0;
}

__device__ __forceinline__ int load_idx(const void* ei, long long pos) {
    if (g_idx64) return (int)((const long long*)ei)[pos];
    return ((const int*)ei)[pos];
}

// ---------------------------------------------------------------------------
// CSR construction
// ---------------------------------------------------------------------------
__global__ void k_zero_deg() {
    int i = blockIdx.x * blockDim.x + threadIdx.x;
    if (i < NN) g_deg[i] = 0;
}

__global__ void k_deg(const void* __restrict__ ei, int e) {
    int i = blockIdx.x * blockDim.x + threadIdx.x;
    if (i < e) atomicAdd(&g_deg[load_idx(ei, (long long)e + i)], 1);
}

// Parallel scan, stage 1: per-block exclusive scan of 1024 elems (smem
// Hillis-Steele); block total -> g_partial[blockIdx].
__global__ __launch_bounds__(1024) void k_scan_block(int n) {
    __shared__ int s[1024];
    int t = threadIdx.x;
    int i = blockIdx.x * 1024 + t;
    int v = (i < n) ? g_deg[i] : 0;
    s[t] = v;
    __syncthreads();
#pragma unroll
    for (int off = 1; off < 1024; off <<= 1) {
        int x = (t >= off) ? s[t - off] : 0;
        __syncthreads();
        s[t] += x;
        __syncthreads();
    }
    if (i < n) g_rowptr[i] = s[t] - v;          // exclusive within block
    if (t == 1023) g_partial[blockIdx.x] = s[1023];
}

// Stage 2: exclusive scan of the 98 block totals (trivial serial).
__global__ void k_scan_top(int nblk) {
    if (threadIdx.x == 0) {
        int run = 0;
        for (int i = 0; i < nblk; i++) {
            int x = g_partial[i];
            g_partial[i] = run;
            run += x;
        }
    }
}

// Stage 3: add block offsets; init cursor + dinv; set rowptr[n].
__global__ void k_finalize(int n, int e) {
    int i = blockIdx.x * blockDim.x + threadIdx.x;
    if (i < n) {
        int r = g_rowptr[i] + g_partial[i >> 10];
        g_rowptr[i] = r;
        g_cursor[i] = r;
        g_dinv[i]   = rsqrtf((float)g_deg[i] + 1.0f);
        if (i == 0) g_rowptr[n] = e;
    }
}

__global__ void k_scatter(const void* __restrict__ ei, int e) {
    int i = blockIdx.x * blockDim.x + threadIdx.x;
    if (i < e) {
        int s = load_idx(ei, i);
        int d = load_idx(ei, (long long)e + i);
        int pos = atomicAdd(&g_cursor[d], 1);
        g_csr[pos] = s;
    }
}

// ---------------------------------------------------------------------------
// GEMM1: g_B1 = (X @ W1) * dinv[row]   (tile 64x128, KT=16, micro 4x8)
// ---------------------------------------------------------------------------
#define TM 64
#define KT 16

__global__ __launch_bounds__(256) void k_gemm1(const float* __restrict__ X,
                                               const float* __restrict__ W) {
    __shared__ float As[TM][KT + 1];
    __shared__ float Bs[KT][HID];
    int row0 = blockIdx.x * TM;
    int t  = threadIdx.x;
    int ty = t >> 4;
    int tx = t & 15;

    float acc[4][8];
#pragma unroll
    for (int r = 0; r < 4; r++)
#pragma unroll
        for (int c = 0; c < 8; c++) acc[r][c] = 0.f;

    for (int k0 = 0; k0 < INCH; k0 += KT) {
        {
            int row = t >> 2;
            int kk  = (t & 3) * 4;
            int gr  = row0 + row;
            float4 v = make_float4(0.f, 0.f, 0.f, 0.f);
            if (gr < NN)
                v = *reinterpret_cast<const float4*>(X + (long long)gr * INCH + k0 + kk);
            As[row][kk]     = v.x;
            As[row][kk + 1] = v.y;
            As[row][kk + 2] = v.z;
            As[row][kk + 3] = v.w;
        }
        {
            int idx = t * 8;
            int kk  = idx >> 7;
            int c   = idx & 127;
            const float* src = W + (long long)(k0 + kk) * HID + c;
            *reinterpret_cast<float4*>(&Bs[kk][c])     = *reinterpret_cast<const float4*>(src);
            *reinterpret_cast<float4*>(&Bs[kk][c + 4]) = *reinterpret_cast<const float4*>(src + 4);
        }
        __syncthreads();
#pragma unroll
        for (int kk = 0; kk < KT; kk++) {
            float a[4];
#pragma unroll
            for (int r = 0; r < 4; r++) a[r] = As[ty * 4 + r][kk];
            float4 b0 = *reinterpret_cast<const float4*>(&Bs[kk][tx * 8]);
            float4 b1 = *reinterpret_cast<const float4*>(&Bs[kk][tx * 8 + 4]);
            float b[8] = {b0.x, b0.y, b0.z, b0.w, b1.x, b1.y, b1.z, b1.w};
#pragma unroll
            for (int r = 0; r < 4; r++)
#pragma unroll
                for (int c = 0; c < 8; c++) acc[r][c] = fmaf(a[r], b[c], acc[r][c]);
        }
        __syncthreads();
    }
#pragma unroll
    for (int r = 0; r < 4; r++) {
        int gr = row0 + ty * 4 + r;
        if (gr < NN) {
            float s = g_dinv[gr];   // pre-scale for norm-factored propagation
            float4 v0 = make_float4(acc[r][0] * s, acc[r][1] * s, acc[r][2] * s, acc[r][3] * s);
            float4 v1 = make_float4(acc[r][4] * s, acc[r][5] * s, acc[r][6] * s, acc[r][7] * s);
            float* dst = g_B1 + (long long)gr * HID + tx * 8;
            *reinterpret_cast<float4*>(dst)     = v0;
            *reinterpret_cast<float4*>(dst + 4) = v1;
        }
    }
}

// ---------------------------------------------------------------------------
// CSR propagation: one warp per node, lane owns one float4 of 128 feats.
// Input rows PRE-SCALED by dinv[src]; multiply by dinv[node] at end.
// ---------------------------------------------------------------------------
__device__ __forceinline__ void prop_body(const float* __restrict__ in,
                                          float* __restrict__ outp,
                                          const float* __restrict__ bias,
                                          int mode) {
    int node = (int)((blockIdx.x * (long long)blockDim.x + threadIdx.x) >> 5);
    int lane = threadIdx.x & 31;
    if (node >= NN) return;

    const float4* IN = (const float4*)in;
    int beg = g_rowptr[node];
    int end = g_rowptr[node + 1];

    float4 acc = IN[(long long)node * 32 + lane];   // self-loop term (pre-scaled)

    int e = beg;
    for (; e + 4 <= end; e += 4) {
        int s0 = g_csr[e];
        int s1 = g_csr[e + 1];
        int s2 = g_csr[e + 2];
        int s3 = g_csr[e + 3];
        float4 v0 = IN[(long long)s0 * 32 + lane];
        float4 v1 = IN[(long long)s1 * 32 + lane];
        float4 v2 = IN[(long long)s2 * 32 + lane];
        float4 v3 = IN[(long long)s3 * 32 + lane];
        acc.x += (v0.x + v1.x) + (v2.x + v3.x);
        acc.y += (v0.y + v1.y) + (v2.y + v3.y);
        acc.z += (v0.z + v1.z) + (v2.z + v3.z);
        acc.w += (v0.w + v1.w) + (v2.w + v3.w);
    }
    for (; e < end; e++) {
        int s = g_csr[e];
        float4 v = IN[(long long)s * 32 + lane];
        acc.x += v.x; acc.y += v.y; acc.z += v.z; acc.w += v.w;
    }

    float dn = g_dinv[node];
    acc.x *= dn; acc.y *= dn; acc.z *= dn; acc.w *= dn;
    if (mode == 1) {
        float4 b = ((const float4*)bias)[lane];
        acc.x = fmaxf(acc.x + b.x, 0.f) * dn;
        acc.y = fmaxf(acc.y + b.y, 0.f) * dn;
        acc.z = fmaxf(acc.z + b.z, 0.f) * dn;
        acc.w = fmaxf(acc.w + b.w, 0.f) * dn;
    }
    ((float4*)outp)[(long long)node * 32 + lane] = acc;
}

// prop1: g_B1 -> g_B2, with bias+relu, output prescaled by dinv
__global__ __launch_bounds__(256) void k_prop1(const float* __restrict__ b1) {
    prop_body(g_B1, g_B2, b1, 1);
}

// prop2: g_B2 -> g_B1, plain aggregation (feeds gemm2)
__global__ __launch_bounds__(256) void k_prop2() {
    prop_body(g_B2, g_B1, (const float*)0, 0);
}

// ---------------------------------------------------------------------------
// GEMM2: [mu | ls] = g_B1 @ [Wmu | Wls] + bias  (g_B1 = A·H, device global)
// ---------------------------------------------------------------------------
__global__ __launch_bounds__(256) void k_gemm2(const float* __restrict__ Wmu,
                                               const float* __restrict__ bmu,
                                               const float* __restrict__ Wls,
                                               const float* __restrict__ bls,
                                               float* __restrict__ out) {
    __shared__ float As[TM][KT + 1];
    __shared__ float Bs[KT][HID];
    int row0 = blockIdx.x * TM;
    int t  = threadIdx.x;
    int ty = t >> 4;
    int tx = t & 15;

    float acc[4][8];
#pragma unroll
    for (int r = 0; r < 4; r++)
#pragma unroll
        for (int c = 0; c < 8; c++) acc[r][c] = 0.f;

    for (int k0 = 0; k0 < HID; k0 += KT) {
        {
            int row = t >> 2;
            int kk  = (t & 3) * 4;
            int gr  = row0 + row;
            float4 v = make_float4(0.f, 0.f, 0.f, 0.f);
            if (gr < NN)
                v = *reinterpret_cast<const float4*>(g_B1 + (long long)gr * HID + k0 + kk);
            As[row][kk]     = v.x;
            As[row][kk + 1] = v.y;
            As[row][kk + 2] = v.z;
            As[row][kk + 3] = v.w;
        }
        {
            int idx = t * 8;
            int kk  = idx >> 7;
            int c   = idx & 127;
            const float* src = (c < 64) ? (Wmu + (long long)(k0 + kk) * OUTC + c)
                                        : (Wls + (long long)(k0 + kk) * OUTC + (c - 64));
            *reinterpret_cast<float4*>(&Bs[kk][c])     = *reinterpret_cast<const float4*>(src);
            *reinterpret_cast<float4*>(&Bs[kk][c + 4]) = *reinterpret_cast<const float4*>(src + 4);
        }
        __syncthreads();
#pragma unroll
        for (int kk = 0; kk < KT; kk++) {
            float a[4];
#pragma unroll
            for (int r = 0; r < 4; r++) a[r] = As[ty * 4 + r][kk];
            float4 b0 = *reinterpret_cast<const float4*>(&Bs[kk][tx * 8]);
            float4 b1 = *reinterpret_cast<const float4*>(&Bs[kk][tx * 8 + 4]);
            float b[8] = {b0.x, b0.y, b0.z, b0.w, b1.x, b1.y, b1.z, b1.w};
#pragma unroll
            for (int r = 0; r < 4; r++)
#pragma unroll
                for (int c = 0; c < 8; c++) acc[r][c] = fmaf(a[r], b[c], acc[r][c]);
        }
        __syncthreads();
    }

    int col0  = tx * 8;
    bool isMu = (col0 < 64);
    int  c0   = isMu ? col0 : (col0 - 64);
    const float* bias = isMu ? bmu : bls;
    float*       base = isMu ? out : (out + (long long)NN * OUTC);
    float4 bv0 = *reinterpret_cast<const float4*>(bias + c0);
    float4 bv1 = *reinterpret_cast<const float4*>(bias + c0 + 4);

#pragma unroll
    for (int r = 0; r < 4; r++) {
        int gr = row0 + ty * 4 + r;
        if (gr < NN) {
            float4 v0 = make_float4(acc[r][0] + bv0.x, acc[r][1] + bv0.y,
                                    acc[r][2] + bv0.z, acc[r][3] + bv0.w);
            float4 v1 = make_float4(acc[r][4] + bv1.x, acc[r][5] + bv1.y,
                                    acc[r][6] + bv1.z, acc[r][7] + bv1.w);
            float* dst = base + (long long)gr * OUTC + c0;
            *reinterpret_cast<float4*>(dst)     = v0;
            *reinterpret_cast<float4*>(dst + 4) = v1;
        }
    }
}

// ---------------------------------------------------------------------------
extern "C" void kernel_launch(void* const* d_in, const int* in_sizes, int n_in,
                              void* d_out, int out_size) {
    const float* x   = (const float*)d_in[0];
    const void*  ei  = d_in[1];
    const float* W1  = (const float*)d_in[2];
    const float* b1  = (const float*)d_in[3];
    const float* Wmu = (const float*)d_in[4];
    const float* bmu = (const float*)d_in[5];
    const float* Wls = (const float*)d_in[6];
    const float* bls = (const float*)d_in[7];
    float* out = (float*)d_out;

    const int E = in_sizes[1] / 2;

    const int nThr    = 256;
    const int nodeBlk = (NN + nThr - 1) / nThr;
    const int edgeBlk = (E + nThr - 1) / nThr;
    const int scanBlk = (NN + 1023) / 1024;   // 98
    const int propBlk = (int)(((long long)NN * 32 + nThr - 1) / nThr);
    const int gemmBlk = (NN + TM - 1) / TM;

    // dtype detection
    k_detect<<<1, 256>>>((const int*)ei);

    // CSR build + dinv (parallel 3-stage scan)
    k_zero_deg<<<nodeBlk, nThr>>>();
    k_deg<<<edgeBlk, nThr>>>(ei, E);
    k_scan_block<<<scanBlk, 1024>>>(NN);
    k_scan_top<<<1, 32>>>(scanBlk);
    k_finalize<<<nodeBlk, nThr>>>(NN, E);
    k_scatter<<<edgeBlk, nThr>>>(ei, E);

    // layer 1: GEMM (dinv-prescaled) -> prop (+bias+relu, prescaled output)
    k_gemm1<<<gemmBlk, nThr>>>(x, W1);
    k_prop1<<<propBlk, nThr>>>(b1);

    // shared propagation for mu/logstd (A linear: A(h@W) = (A h)@W)
    k_prop2<<<propBlk, nThr>>>();

    // dual output GEMM with bias
    k_gemm2<<<gemmBlk, nThr>>>(Wmu, bmu, Wls, bls, out);
}

// round 6
// speedup vs baseline: 2.8725x; 1.3051x over previous
#include <cuda_runtime.h>

#define NN    100000
#define EEMAX 4000000
#define INCH  256
#define HID   128
#define OUTC  64
#define FULLMASK 0xffffffffu

// -------- scratch (device globals; referenced ONLY from device code) --------
__device__ float g_B1[(size_t)NN * HID];
__device__ float g_B2[(size_t)NN * HID];
__device__ float g_dinv[NN];
__device__ int   g_deg[NN];
__device__ int   g_rowptr[NN + 1];
__device__ int   g_cursor[NN];
__device__ int   g_csr[EEMAX];
__device__ int   g_partial[128];
__device__ int   g_idx64;

// ---------------------------------------------------------------------------
// edge_index dtype detection (int64 vs int32)
// ---------------------------------------------------------------------------
__global__ void k_detect(const int* __restrict__ ei32) {
    __shared__ int nz;
    if (threadIdx.x == 0) nz = 0;
    __syncthreads();
    int local = 0;
    for (int i = threadIdx.x; i < 4096; i += blockDim.x)
        if (ei32[2 * i + 1] != 0) local = 1;
    if (local) atomicOr(&nz, 1);
    __syncthreads();
    if (threadIdx.x == 0) g_idx64 = (nz == 0) ? 1 : 0;
}

__device__ __forceinline__ int load_idx(const void* ei, long long pos) {
    if (g_idx64) return (int)((const long long*)ei)[pos];
    return ((const int*)ei)[pos];
}

// ---------------------------------------------------------------------------
// CSR construction
// ---------------------------------------------------------------------------
__global__ void k_zero_deg() {
    int i = blockIdx.x * blockDim.x + threadIdx.x;
    if (i < NN) g_deg[i] = 0;
}

__global__ void k_deg(const void* __restrict__ ei, int e) {
    int i = blockIdx.x * blockDim.x + threadIdx.x;
    if (i < e) atomicAdd(&g_deg[load_idx(ei, (long long)e + i)], 1);
}

__global__ __launch_bounds__(1024) void k_scan_block(int n) {
    __shared__ int s[1024];
    int t = threadIdx.x;
    int i = blockIdx.x * 1024 + t;
    int v = (i < n) ? g_deg[i] : 0;
    s[t] = v;
    __syncthreads();
#pragma unroll
    for (int off = 1; off < 1024; off <<= 1) {
        int x = (t >= off) ? s[t - off] : 0;
        __syncthreads();
        s[t] += x;
        __syncthreads();
    }
    if (i < n) g_rowptr[i] = s[t] - v;
    if (t == 1023) g_partial[blockIdx.x] = s[1023];
}

__global__ void k_scan_top(int nblk) {
    if (threadIdx.x == 0) {
        int run = 0;
        for (int i = 0; i < nblk; i++) {
            int x = g_partial[i];
            g_partial[i] = run;
            run += x;
        }
    }
}

__global__ void k_finalize(int n, int e) {
    int i = blockIdx.x * blockDim.x + threadIdx.x;
    if (i < n) {
        int r = g_rowptr[i] + g_partial[i >> 10];
        g_rowptr[i] = r;
        g_cursor[i] = r;
        g_dinv[i]   = rsqrtf((float)g_deg[i] + 1.0f);
        if (i == 0) g_rowptr[n] = e;
    }
}

__global__ void k_scatter(const void* __restrict__ ei, int e) {
    int i = blockIdx.x * blockDim.x + threadIdx.x;
    if (i < e) {
        int s = load_idx(ei, i);
        int d = load_idx(ei, (long long)e + i);
        int pos = atomicAdd(&g_cursor[d], 1);
        g_csr[pos] = s;
    }
}

// ---------------------------------------------------------------------------
// GEMM1: g_B1 = (X @ W1) * dinv[row]
// 128x128 tile, KT=16, 256 threads, 8x8 micro-tile, reg double-buffer.
// A stored K-major in smem (As[kk][row]) -> conflict-free LDS.128 in compute.
// ---------------------------------------------------------------------------
#define KT  16
#define TMR 128

__global__ __launch_bounds__(256, 2) void k_gemm1(const float* __restrict__ X,
                                                  const float* __restrict__ W) {
    __shared__ float As[KT][TMR];
    __shared__ float Bs[KT][HID];
    int t = threadIdx.x;
    int row0 = blockIdx.x * TMR;

    int arow = t >> 1, akk = (t & 1) * 8;
    int gr_a = row0 + arow;
    int bkk = t >> 4, bc = (t & 15) * 8;

    int ty = t >> 4, tx = t & 15;
    int rA0 = ty * 4, rA1 = 64 + ty * 4;
    int cB0 = tx * 4, cB1 = 64 + tx * 4;

    float acc[8][8];
#pragma unroll
    for (int r = 0; r < 8; r++)
#pragma unroll
        for (int c = 0; c < 8; c++) acc[r][c] = 0.f;

    float4 ra0 = make_float4(0, 0, 0, 0), ra1 = ra0, rb0, rb1;
    if (gr_a < NN) {
        const float* p = X + (long long)gr_a * INCH + akk;
        ra0 = *(const float4*)p;
        ra1 = *(const float4*)(p + 4);
    }
    {
        const float* p = W + (long long)bkk * HID + bc;
        rb0 = *(const float4*)p;
        rb1 = *(const float4*)(p + 4);
    }

    for (int k0 = 0; k0 < INCH; k0 += KT) {
        As[akk + 0][arow] = ra0.x; As[akk + 1][arow] = ra0.y;
        As[akk + 2][arow] = ra0.z; As[akk + 3][arow] = ra0.w;
        As[akk + 4][arow] = ra1.x; As[akk + 5][arow] = ra1.y;
        As[akk + 6][arow] = ra1.z; As[akk + 7][arow] = ra1.w;
        *(float4*)&Bs[bkk][bc]     = rb0;
        *(float4*)&Bs[bkk][bc + 4] = rb1;
        __syncthreads();

        int kn = k0 + KT;
        if (kn < INCH) {
            if (gr_a < NN) {
                const float* p = X + (long long)gr_a * INCH + kn + akk;
                ra0 = *(const float4*)p;
                ra1 = *(const float4*)(p + 4);
            }
            const float* p = W + (long long)(kn + bkk) * HID + bc;
            rb0 = *(const float4*)p;
            rb1 = *(const float4*)(p + 4);
        }

#pragma unroll
        for (int kk = 0; kk < KT; kk++) {
            float4 a0 = *(const float4*)&As[kk][rA0];
            float4 a1 = *(const float4*)&As[kk][rA1];
            float4 b0 = *(const float4*)&Bs[kk][cB0];
            float4 b1 = *(const float4*)&Bs[kk][cB1];
            float av[8] = {a0.x, a0.y, a0.z, a0.w, a1.x, a1.y, a1.z, a1.w};
            float bv[8] = {b0.x, b0.y, b0.z, b0.w, b1.x, b1.y, b1.z, b1.w};
#pragma unroll
            for (int r = 0; r < 8; r++)
#pragma unroll
                for (int c = 0; c < 8; c++)
                    acc[r][c] = fmaf(av[r], bv[c], acc[r][c]);
        }
        __syncthreads();
    }

#pragma unroll
    for (int r = 0; r < 8; r++) {
        int gr = row0 + ((r < 4) ? (rA0 + r) : (rA1 + r - 4));
        if (gr < NN) {
            float s = g_dinv[gr];   // pre-scale for norm-factored propagation
            float4 v0 = make_float4(acc[r][0] * s, acc[r][1] * s, acc[r][2] * s, acc[r][3] * s);
            float4 v1 = make_float4(acc[r][4] * s, acc[r][5] * s, acc[r][6] * s, acc[r][7] * s);
            float* dst = g_B1 + (long long)gr * HID;
            *(float4*)(dst + cB0) = v0;
            *(float4*)(dst + cB1) = v1;
        }
    }
}

// ---------------------------------------------------------------------------
// CSR propagation: warp per node; 8-edge unroll for MLP.
// ---------------------------------------------------------------------------
__device__ __forceinline__ void prop_body(const float* __restrict__ in,
                                          float* __restrict__ outp,
                                          const float* __restrict__ bias,
                                          int mode) {
    int node = (int)((blockIdx.x * (long long)blockDim.x + threadIdx.x) >> 5);
    int lane = threadIdx.x & 31;
    if (node >= NN) return;

    const float4* IN = (const float4*)in;
    int beg = g_rowptr[node];
    int end = g_rowptr[node + 1];

    float4 acc = IN[(long long)node * 32 + lane];   // self-loop (pre-scaled)

    int e = beg;
    for (; e + 8 <= end; e += 8) {
        int s0 = g_csr[e];
        int s1 = g_csr[e + 1];
        int s2 = g_csr[e + 2];
        int s3 = g_csr[e + 3];
        int s4 = g_csr[e + 4];
        int s5 = g_csr[e + 5];
        int s6 = g_csr[e + 6];
        int s7 = g_csr[e + 7];
        float4 v0 = IN[(long long)s0 * 32 + lane];
        float4 v1 = IN[(long long)s1 * 32 + lane];
        float4 v2 = IN[(long long)s2 * 32 + lane];
        float4 v3 = IN[(long long)s3 * 32 + lane];
        float4 v4 = IN[(long long)s4 * 32 + lane];
        float4 v5 = IN[(long long)s5 * 32 + lane];
        float4 v6 = IN[(long long)s6 * 32 + lane];
        float4 v7 = IN[(long long)s7 * 32 + lane];
        acc.x += ((v0.x + v1.x) + (v2.x + v3.x)) + ((v4.x + v5.x) + (v6.x + v7.x));
        acc.y += ((v0.y + v1.y) + (v2.y + v3.y)) + ((v4.y + v5.y) + (v6.y + v7.y));
        acc.z += ((v0.z + v1.z) + (v2.z + v3.z)) + ((v4.z + v5.z) + (v6.z + v7.z));
        acc.w += ((v0.w + v1.w) + (v2.w + v3.w)) + ((v4.w + v5.w) + (v6.w + v7.w));
    }
    for (; e + 4 <= end; e += 4) {
        int s0 = g_csr[e];
        int s1 = g_csr[e + 1];
        int s2 = g_csr[e + 2];
        int s3 = g_csr[e + 3];
        float4 v0 = IN[(long long)s0 * 32 + lane];
        float4 v1 = IN[(long long)s1 * 32 + lane];
        float4 v2 = IN[(long long)s2 * 32 + lane];
        float4 v3 = IN[(long long)s3 * 32 + lane];
        acc.x += (v0.x + v1.x) + (v2.x + v3.x);
        acc.y += (v0.y + v1.y) + (v2.y + v3.y);
        acc.z += (v0.z + v1.z) + (v2.z + v3.z);
        acc.w += (v0.w + v1.w) + (v2.w + v3.w);
    }
    for (; e < end; e++) {
        int s = g_csr[e];
        float4 v = IN[(long long)s * 32 + lane];
        acc.x += v.x; acc.y += v.y; acc.z += v.z; acc.w += v.w;
    }

    float dn = g_dinv[node];
    acc.x *= dn; acc.y *= dn; acc.z *= dn; acc.w *= dn;
    if (mode == 1) {
        float4 b = ((const float4*)bias)[lane];
        acc.x = fmaxf(acc.x + b.x, 0.f) * dn;
        acc.y = fmaxf(acc.y + b.y, 0.f) * dn;
        acc.z = fmaxf(acc.z + b.z, 0.f) * dn;
        acc.w = fmaxf(acc.w + b.w, 0.f) * dn;
    }
    ((float4*)outp)[(long long)node * 32 + lane] = acc;
}

__global__ __launch_bounds__(256) void k_prop1(const float* __restrict__ b1) {
    prop_body(g_B1, g_B2, b1, 1);
}

__global__ __launch_bounds__(256) void k_prop2() {
    prop_body(g_B2, g_B1, (const float*)0, 0);
}

// ---------------------------------------------------------------------------
// GEMM2: [mu | ls] = g_B1 @ [Wmu | Wls] + bias
// Same 128x128 double-buffered structure; cB0 -> mu cols, cB1 -> ls cols.
// ---------------------------------------------------------------------------
__global__ __launch_bounds__(256, 2) void k_gemm2(const float* __restrict__ Wmu,
                                                  const float* __restrict__ bmu,
                                                  const float* __restrict__ Wls,
                                                  const float* __restrict__ bls,
                                                  float* __restrict__ out) {
    __shared__ float As[KT][TMR];
    __shared__ float Bs[KT][HID];
    int t = threadIdx.x;
    int row0 = blockIdx.x * TMR;

    int arow = t >> 1, akk = (t & 1) * 8;
    int gr_a = row0 + arow;
    int bkk = t >> 4, bc = (t & 15) * 8;

    int ty = t >> 4, tx = t & 15;
    int rA0 = ty * 4, rA1 = 64 + ty * 4;
    int cB0 = tx * 4, cB1 = 64 + tx * 4;

    float acc[8][8];
#pragma unroll
    for (int r = 0; r < 8; r++)
#pragma unroll
        for (int c = 0; c < 8; c++) acc[r][c] = 0.f;

    float4 ra0 = make_float4(0, 0, 0, 0), ra1 = ra0, rb0, rb1;
    if (gr_a < NN) {
        const float* p = g_B1 + (long long)gr_a * HID + akk;
        ra0 = *(const float4*)p;
        ra1 = *(const float4*)(p + 4);
    }
    {
        const float* p = (bc < 64) ? (Wmu + (long long)bkk * OUTC + bc)
                                   : (Wls + (long long)bkk * OUTC + (bc - 64));
        rb0 = *(const float4*)p;
        rb1 = *(const float4*)(p + 4);
    }

    for (int k0 = 0; k0 < HID; k0 += KT) {
        As[akk + 0][arow] = ra0.x; As[akk + 1][arow] = ra0.y;
        As[akk + 2][arow] = ra0.z; As[akk + 3][arow] = ra0.w;
        As[akk + 4][arow] = ra1.x; As[akk + 5][arow] = ra1.y;
        As[akk + 6][arow] = ra1.z; As[akk + 7][arow] = ra1.w;
        *(float4*)&Bs[bkk][bc]     = rb0;
        *(float4*)&Bs[bkk][bc + 4] = rb1;
        __syncthreads();

        int kn = k0 + KT;
        if (kn < HID) {
            if (gr_a < NN) {
                const float* p = g_B1 + (long long)gr_a * HID + kn + akk;
                ra0 = *(const float4*)p;
                ra1 = *(const float4*)(p + 4);
            }
            const float* p = (bc < 64) ? (Wmu + (long long)(kn + bkk) * OUTC + bc)
                                       : (Wls + (long long)(kn + bkk) * OUTC + (bc - 64));
            rb0 = *(const float4*)p;
            rb1 = *(const float4*)(p + 4);
        }

#pragma unroll
        for (int kk = 0; kk < KT; kk++) {
            float4 a0 = *(const float4*)&As[kk][rA0];
            float4 a1 = *(const float4*)&As[kk][rA1];
            float4 b0 = *(const float4*)&Bs[kk][cB0];
            float4 b1 = *(const float4*)&Bs[kk][cB1];
            float av[8] = {a0.x, a0.y, a0.z, a0.w, a1.x, a1.y, a1.z, a1.w};
            float bv[8] = {b0.x, b0.y, b0.z, b0.w, b1.x, b1.y, b1.z, b1.w};
#pragma unroll
            for (int r = 0; r < 8; r++)
#pragma unroll
                for (int c = 0; c < 8; c++)
                    acc[r][c] = fmaf(av[r], bv[c], acc[r][c]);
        }
        __syncthreads();
    }

    // cB0 in [0,64): mu columns; cB1 in [64,128): ls columns
    float4 bv0 = *(const float4*)(bmu + cB0);
    float4 bv1 = *(const float4*)(bls + (cB1 - 64));
#pragma unroll
    for (int r = 0; r < 8; r++) {
        int gr = row0 + ((r < 4) ? (rA0 + r) : (rA1 + r - 4));
        if (gr < NN) {
            float4 v0 = make_float4(acc[r][0] + bv0.x, acc[r][1] + bv0.y,
                                    acc[r][2] + bv0.z, acc[r][3] + bv0.w);
            float4 v1 = make_float4(acc[r][4] + bv1.x, acc[r][5] + bv1.y,
                                    acc[r][6] + bv1.z, acc[r][7] + bv1.w);
            *(float4*)(out + (long long)gr * OUTC + cB0) = v0;
            *(float4*)(out + (long long)NN * OUTC + (long long)gr * OUTC + (cB1 - 64)) = v1;
        }
    }
}

// ---------------------------------------------------------------------------
extern "C" void kernel_launch(void* const* d_in, const int* in_sizes, int n_in,
                              void* d_out, int out_size) {
    const float* x   = (const float*)d_in[0];
    const void*  ei  = d_in[1];
    const float* W1  = (const float*)d_in[2];
    const float* b1  = (const float*)d_in[3];
    const float* Wmu = (const float*)d_in[4];
    const float* bmu = (const float*)d_in[5];
    const float* Wls = (const float*)d_in[6];
    const float* bls = (const float*)d_in[7];
    float* out = (float*)d_out;

    const int E = in_sizes[1] / 2;

    const int nThr    = 256;
    const int nodeBlk = (NN + nThr - 1) / nThr;
    const int edgeBlk = (E + nThr - 1) / nThr;
    const int scanBlk = (NN + 1023) / 1024;   // 98
    const int propBlk = (int)(((long long)NN * 32 + nThr - 1) / nThr);
    const int gemmBlk = (NN + TMR - 1) / TMR;  // 782

    // dtype detection
    k_detect<<<1, 256>>>((const int*)ei);

    // CSR build + dinv (parallel 3-stage scan)
    k_zero_deg<<<nodeBlk, nThr>>>();
    k_deg<<<edgeBlk, nThr>>>(ei, E);
    k_scan_block<<<scanBlk, 1024>>>(NN);
    k_scan_top<<<1, 32>>>(scanBlk);
    k_finalize<<<nodeBlk, nThr>>>(NN, E);
    k_scatter<<<edgeBlk, nThr>>>(ei, E);

    // layer 1: GEMM (dinv-prescaled) -> prop (+bias+relu, prescaled output)
    k_gemm1<<<gemmBlk, nThr>>>(x, W1);
    k_prop1<<<propBlk, nThr>>>(b1);

    // shared propagation for mu/logstd (A linear: A(h@W) = (A h)@W)
    k_prop2<<<propBlk, nThr>>>();

    // dual output GEMM with bias
    k_gemm2<<<gemmBlk, nThr>>>(Wmu, bmu, Wls, bls, out);
}

// round 7
// speedup vs baseline: 3.2060x; 1.1161x over previous
#include <cuda_runtime.h>
#include <cuda_fp16.h>

#define NN    100000
#define EEMAX 4000000
#define INCH  256
#define HID   128
#define OUTC  64
#define FULLMASK 0xffffffffu

// -------- scratch (device globals; referenced ONLY from device code) --------
__device__ __half g_H16a[(size_t)NN * HID];   // gemm1 out (prescaled, fp16)
__device__ __half g_H16b[(size_t)NN * HID];   // prop1 out (prescaled, fp16)
__device__ float  g_B1[(size_t)NN * HID];     // prop2 out (fp32, feeds gemm2)
__device__ float  g_dinv[NN];
__device__ int    g_deg[NN];
__device__ int    g_rowptr[NN + 1];
__device__ int    g_cursor[NN];
__device__ int    g_csr[EEMAX];
__device__ int    g_partial[128];
__device__ int    g_idx64;

// ---------------------------------------------------------------------------
// fp16 pack/unpack helpers (4 halves <-> float4 via uint2)
// ---------------------------------------------------------------------------
__device__ __forceinline__ float4 h4_to_f4(uint2 u) {
    __half2 h0 = *reinterpret_cast<__half2*>(&u.x);
    __half2 h1 = *reinterpret_cast<__half2*>(&u.y);
    float2 f0 = __half22float2(h0);
    float2 f1 = __half22float2(h1);
    return make_float4(f0.x, f0.y, f1.x, f1.y);
}

__device__ __forceinline__ uint2 f4_to_h4(float4 v) {
    __half2 h0 = __floats2half2_rn(v.x, v.y);
    __half2 h1 = __floats2half2_rn(v.z, v.w);
    uint2 u;
    u.x = *reinterpret_cast<unsigned*>(&h0);
    u.y = *reinterpret_cast<unsigned*>(&h1);
    return u;
}

// ---------------------------------------------------------------------------
// edge_index dtype detection (int64 vs int32)
// ---------------------------------------------------------------------------
__global__ void k_detect(const int* __restrict__ ei32) {
    __shared__ int nz;
    if (threadIdx.x == 0) nz = 0;
    __syncthreads();
    int local = 0;
    for (int i = threadIdx.x; i < 4096; i += blockDim.x)
        if (ei32[2 * i + 1] != 0) local = 1;
    if (local) atomicOr(&nz, 1);
    __syncthreads();
    if (threadIdx.x == 0) g_idx64 = (nz == 0) ? 1 : 0;
}

__device__ __forceinline__ int load_idx(const void* ei, long long pos) {
    if (g_idx64) return (int)((const long long*)ei)[pos];
    return ((const int*)ei)[pos];
}

// ---------------------------------------------------------------------------
// CSR construction
// ---------------------------------------------------------------------------
__global__ void k_zero_deg() {
    int i = blockIdx.x * blockDim.x + threadIdx.x;
    if (i < NN) g_deg[i] = 0;
}

__global__ void k_deg(const void* __restrict__ ei, int e) {
    int i = blockIdx.x * blockDim.x + threadIdx.x;
    if (i < e) atomicAdd(&g_deg[load_idx(ei, (long long)e + i)], 1);
}

__global__ __launch_bounds__(1024) void k_scan_block(int n) {
    __shared__ int s[1024];
    int t = threadIdx.x;
    int i = blockIdx.x * 1024 + t;
    int v = (i < n) ? g_deg[i] : 0;
    s[t] = v;
    __syncthreads();
#pragma unroll
    for (int off = 1; off < 1024; off <<= 1) {
        int x = (t >= off) ? s[t - off] : 0;
        __syncthreads();
        s[t] += x;
        __syncthreads();
    }
    if (i < n) g_rowptr[i] = s[t] - v;
    if (t == 1023) g_partial[blockIdx.x] = s[1023];
}

__global__ void k_scan_top(int nblk) {
    if (threadIdx.x == 0) {
        int run = 0;
        for (int i = 0; i < nblk; i++) {
            int x = g_partial[i];
            g_partial[i] = run;
            run += x;
        }
    }
}

__global__ void k_finalize(int n, int e) {
    int i = blockIdx.x * blockDim.x + threadIdx.x;
    if (i < n) {
        int r = g_rowptr[i] + g_partial[i >> 10];
        g_rowptr[i] = r;
        g_cursor[i] = r;
        g_dinv[i]   = rsqrtf((float)g_deg[i] + 1.0f);
        if (i == 0) g_rowptr[n] = e;
    }
}

__global__ void k_scatter(const void* __restrict__ ei, int e) {
    int i = blockIdx.x * blockDim.x + threadIdx.x;
    if (i < e) {
        int s = load_idx(ei, i);
        int d = load_idx(ei, (long long)e + i);
        int pos = atomicAdd(&g_cursor[d], 1);
        g_csr[pos] = s;
    }
}

// ---------------------------------------------------------------------------
// GEMM1: g_H16a = fp16( (X @ W1) * dinv[row] )
// 128x128 tile, KT=16, 256 threads, 8x8 micro-tile, reg double-buffer.
// ---------------------------------------------------------------------------
#define KT  16
#define TMR 128

__global__ __launch_bounds__(256, 2) void k_gemm1(const float* __restrict__ X,
                                                  const float* __restrict__ W) {
    __shared__ float As[KT][TMR];
    __shared__ float Bs[KT][HID];
    int t = threadIdx.x;
    int row0 = blockIdx.x * TMR;

    int arow = t >> 1, akk = (t & 1) * 8;
    int gr_a = row0 + arow;
    int bkk = t >> 4, bc = (t & 15) * 8;

    int ty = t >> 4, tx = t & 15;
    int rA0 = ty * 4, rA1 = 64 + ty * 4;
    int cB0 = tx * 4, cB1 = 64 + tx * 4;

    float acc[8][8];
#pragma unroll
    for (int r = 0; r < 8; r++)
#pragma unroll
        for (int c = 0; c < 8; c++) acc[r][c] = 0.f;

    float4 ra0 = make_float4(0, 0, 0, 0), ra1 = ra0, rb0, rb1;
    if (gr_a < NN) {
        const float* p = X + (long long)gr_a * INCH + akk;
        ra0 = *(const float4*)p;
        ra1 = *(const float4*)(p + 4);
    }
    {
        const float* p = W + (long long)bkk * HID + bc;
        rb0 = *(const float4*)p;
        rb1 = *(const float4*)(p + 4);
    }

    for (int k0 = 0; k0 < INCH; k0 += KT) {
        As[akk + 0][arow] = ra0.x; As[akk + 1][arow] = ra0.y;
        As[akk + 2][arow] = ra0.z; As[akk + 3][arow] = ra0.w;
        As[akk + 4][arow] = ra1.x; As[akk + 5][arow] = ra1.y;
        As[akk + 6][arow] = ra1.z; As[akk + 7][arow] = ra1.w;
        *(float4*)&Bs[bkk][bc]     = rb0;
        *(float4*)&Bs[bkk][bc + 4] = rb1;
        __syncthreads();

        int kn = k0 + KT;
        if (kn < INCH) {
            if (gr_a < NN) {
                const float* p = X + (long long)gr_a * INCH + kn + akk;
                ra0 = *(const float4*)p;
                ra1 = *(const float4*)(p + 4);
            }
            const float* p = W + (long long)(kn + bkk) * HID + bc;
            rb0 = *(const float4*)p;
            rb1 = *(const float4*)(p + 4);
        }

#pragma unroll
        for (int kk = 0; kk < KT; kk++) {
            float4 a0 = *(const float4*)&As[kk][rA0];
            float4 a1 = *(const float4*)&As[kk][rA1];
            float4 b0 = *(const float4*)&Bs[kk][cB0];
            float4 b1 = *(const float4*)&Bs[kk][cB1];
            float av[8] = {a0.x, a0.y, a0.z, a0.w, a1.x, a1.y, a1.z, a1.w};
            float bv[8] = {b0.x, b0.y, b0.z, b0.w, b1.x, b1.y, b1.z, b1.w};
#pragma unroll
            for (int r = 0; r < 8; r++)
#pragma unroll
                for (int c = 0; c < 8; c++)
                    acc[r][c] = fmaf(av[r], bv[c], acc[r][c]);
        }
        __syncthreads();
    }

#pragma unroll
    for (int r = 0; r < 8; r++) {
        int gr = row0 + ((r < 4) ? (rA0 + r) : (rA1 + r - 4));
        if (gr < NN) {
            float s = g_dinv[gr];   // pre-scale for norm-factored propagation
            float4 v0 = make_float4(acc[r][0] * s, acc[r][1] * s, acc[r][2] * s, acc[r][3] * s);
            float4 v1 = make_float4(acc[r][4] * s, acc[r][5] * s, acc[r][6] * s, acc[r][7] * s);
            __half* dst = g_H16a + (long long)gr * HID;
            *(uint2*)(dst + cB0) = f4_to_h4(v0);
            *(uint2*)(dst + cB1) = f4_to_h4(v1);
        }
    }
}

// ---------------------------------------------------------------------------
// CSR propagation (fp16 gather, fp32 accumulate): warp per node.
// Row = 128 halves = 32 uint2; lane owns uint2 (4 feats).
// mode=1: out fp16 = h( dinv*relu(dn*sum + b1) )    -> g_H16b
// mode=0: out fp32 = dn*sum                          -> outf
// ---------------------------------------------------------------------------
__device__ __forceinline__ void prop_body_h(const __half* __restrict__ in,
                                            __half* __restrict__ outh,
                                            float* __restrict__ outf,
                                            const float* __restrict__ bias,
                                            int mode) {
    int node = (int)((blockIdx.x * (long long)blockDim.x + threadIdx.x) >> 5);
    int lane = threadIdx.x & 31;
    if (node >= NN) return;

    const uint2* IN = (const uint2*)in;
    int beg = g_rowptr[node];
    int end = g_rowptr[node + 1];

    float4 acc = h4_to_f4(IN[(long long)node * 32 + lane]);  // self-loop (pre-scaled)

    int e = beg;
    for (; e + 8 <= end; e += 8) {
        int s0 = g_csr[e];
        int s1 = g_csr[e + 1];
        int s2 = g_csr[e + 2];
        int s3 = g_csr[e + 3];
        int s4 = g_csr[e + 4];
        int s5 = g_csr[e + 5];
        int s6 = g_csr[e + 6];
        int s7 = g_csr[e + 7];
        uint2 u0 = IN[(long long)s0 * 32 + lane];
        uint2 u1 = IN[(long long)s1 * 32 + lane];
        uint2 u2 = IN[(long long)s2 * 32 + lane];
        uint2 u3 = IN[(long long)s3 * 32 + lane];
        uint2 u4 = IN[(long long)s4 * 32 + lane];
        uint2 u5 = IN[(long long)s5 * 32 + lane];
        uint2 u6 = IN[(long long)s6 * 32 + lane];
        uint2 u7 = IN[(long long)s7 * 32 + lane];
        float4 v0 = h4_to_f4(u0), v1 = h4_to_f4(u1), v2 = h4_to_f4(u2), v3 = h4_to_f4(u3);
        float4 v4 = h4_to_f4(u4), v5 = h4_to_f4(u5), v6 = h4_to_f4(u6), v7 = h4_to_f4(u7);
        acc.x += ((v0.x + v1.x) + (v2.x + v3.x)) + ((v4.x + v5.x) + (v6.x + v7.x));
        acc.y += ((v0.y + v1.y) + (v2.y + v3.y)) + ((v4.y + v5.y) + (v6.y + v7.y));
        acc.z += ((v0.z + v1.z) + (v2.z + v3.z)) + ((v4.z + v5.z) + (v6.z + v7.z));
        acc.w += ((v0.w + v1.w) + (v2.w + v3.w)) + ((v4.w + v5.w) + (v6.w + v7.w));
    }
    for (; e + 4 <= end; e += 4) {
        int s0 = g_csr[e];
        int s1 = g_csr[e + 1];
        int s2 = g_csr[e + 2];
        int s3 = g_csr[e + 3];
        float4 v0 = h4_to_f4(IN[(long long)s0 * 32 + lane]);
        float4 v1 = h4_to_f4(IN[(long long)s1 * 32 + lane]);
        float4 v2 = h4_to_f4(IN[(long long)s2 * 32 + lane]);
        float4 v3 = h4_to_f4(IN[(long long)s3 * 32 + lane]);
        acc.x += (v0.x + v1.x) + (v2.x + v3.x);
        acc.y += (v0.y + v1.y) + (v2.y + v3.y);
        acc.z += (v0.z + v1.z) + (v2.z + v3.z);
        acc.w += (v0.w + v1.w) + (v2.w + v3.w);
    }
    for (; e < end; e++) {
        int s = g_csr[e];
        float4 v = h4_to_f4(IN[(long long)s * 32 + lane]);
        acc.x += v.x; acc.y += v.y; acc.z += v.z; acc.w += v.w;
    }

    float dn = g_dinv[node];
    acc.x *= dn; acc.y *= dn; acc.z *= dn; acc.w *= dn;
    if (mode == 1) {
        float4 b = ((const float4*)bias)[lane];
        acc.x = fmaxf(acc.x + b.x, 0.f) * dn;
        acc.y = fmaxf(acc.y + b.y, 0.f) * dn;
        acc.z = fmaxf(acc.z + b.z, 0.f) * dn;
        acc.w = fmaxf(acc.w + b.w, 0.f) * dn;
        ((uint2*)outh)[(long long)node * 32 + lane] = f4_to_h4(acc);
    } else {
        ((float4*)outf)[(long long)node * 32 + lane] = acc;
    }
}

// prop1: g_H16a -> g_H16b (fp16, bias+relu, prescaled)
__global__ __launch_bounds__(256) void k_prop1(const float* __restrict__ b1) {
    prop_body_h(g_H16a, g_H16b, (float*)0, b1, 1);
}

// prop2: g_H16b -> g_B1 (fp32, feeds gemm2)
__global__ __launch_bounds__(256) void k_prop2() {
    prop_body_h(g_H16b, (__half*)0, g_B1, (const float*)0, 0);
}

// ---------------------------------------------------------------------------
// GEMM2: [mu | ls] = g_B1 @ [Wmu | Wls] + bias
// ---------------------------------------------------------------------------
__global__ __launch_bounds__(256, 2) void k_gemm2(const float* __restrict__ Wmu,
                                                  const float* __restrict__ bmu,
                                                  const float* __restrict__ Wls,
                                                  const float* __restrict__ bls,
                                                  float* __restrict__ out) {
    __shared__ float As[KT][TMR];
    __shared__ float Bs[KT][HID];
    int t = threadIdx.x;
    int row0 = blockIdx.x * TMR;

    int arow = t >> 1, akk = (t & 1) * 8;
    int gr_a = row0 + arow;
    int bkk = t >> 4, bc = (t & 15) * 8;

    int ty = t >> 4, tx = t & 15;
    int rA0 = ty * 4, rA1 = 64 + ty * 4;
    int cB0 = tx * 4, cB1 = 64 + tx * 4;

    float acc[8][8];
#pragma unroll
    for (int r = 0; r < 8; r++)
#pragma unroll
        for (int c = 0; c < 8; c++) acc[r][c] = 0.f;

    float4 ra0 = make_float4(0, 0, 0, 0), ra1 = ra0, rb0, rb1;
    if (gr_a < NN) {
        const float* p = g_B1 + (long long)gr_a * HID + akk;
        ra0 = *(const float4*)p;
        ra1 = *(const float4*)(p + 4);
    }
    {
        const float* p = (bc < 64) ? (Wmu + (long long)bkk * OUTC + bc)
                                   : (Wls + (long long)bkk * OUTC + (bc - 64));
        rb0 = *(const float4*)p;
        rb1 = *(const float4*)(p + 4);
    }

    for (int k0 = 0; k0 < HID; k0 += KT) {
        As[akk + 0][arow] = ra0.x; As[akk + 1][arow] = ra0.y;
        As[akk + 2][arow] = ra0.z; As[akk + 3][arow] = ra0.w;
        As[akk + 4][arow] = ra1.x; As[akk + 5][arow] = ra1.y;
        As[akk + 6][arow] = ra1.z; As[akk + 7][arow] = ra1.w;
        *(float4*)&Bs[bkk][bc]     = rb0;
        *(float4*)&Bs[bkk][bc + 4] = rb1;
        __syncthreads();

        int kn = k0 + KT;
        if (kn < HID) {
            if (gr_a < NN) {
                const float* p = g_B1 + (long long)gr_a * HID + kn + akk;
                ra0 = *(const float4*)p;
                ra1 = *(const float4*)(p + 4);
            }
            const float* p = (bc < 64) ? (Wmu + (long long)(kn + bkk) * OUTC + bc)
                                       : (Wls + (long long)(kn + bkk) * OUTC + (bc - 64));
            rb0 = *(const float4*)p;
            rb1 = *(const float4*)(p + 4);
        }

#pragma unroll
        for (int kk = 0; kk < KT; kk++) {
            float4 a0 = *(const float4*)&As[kk][rA0];
            float4 a1 = *(const float4*)&As[kk][rA1];
            float4 b0 = *(const float4*)&Bs[kk][cB0];
            float4 b1 = *(const float4*)&Bs[kk][cB1];
            float av[8] = {a0.x, a0.y, a0.z, a0.w, a1.x, a1.y, a1.z, a1.w};
            float bv[8] = {b0.x, b0.y, b0.z, b0.w, b1.x, b1.y, b1.z, b1.w};
#pragma unroll
            for (int r = 0; r < 8; r++)
#pragma unroll
                for (int c = 0; c < 8; c++)
                    acc[r][c] = fmaf(av[r], bv[c], acc[r][c]);
        }
        __syncthreads();
    }

    // cB0 in [0,64): mu columns; cB1 in [64,128): ls columns
    float4 bv0 = *(const float4*)(bmu + cB0);
    float4 bv1 = *(const float4*)(bls + (cB1 - 64));
#pragma unroll
    for (int r = 0; r < 8; r++) {
        int gr = row0 + ((r < 4) ? (rA0 + r) : (rA1 + r - 4));
        if (gr < NN) {
            float4 v0 = make_float4(acc[r][0] + bv0.x, acc[r][1] + bv0.y,
                                    acc[r][2] + bv0.z, acc[r][3] + bv0.w);
            float4 v1 = make_float4(acc[r][4] + bv1.x, acc[r][5] + bv1.y,
                                    acc[r][6] + bv1.z, acc[r][7] + bv1.w);
            *(float4*)(out + (long long)gr * OUTC + cB0) = v0;
            *(float4*)(out + (long long)NN * OUTC + (long long)gr * OUTC + (cB1 - 64)) = v1;
        }
    }
}

// ---------------------------------------------------------------------------
extern "C" void kernel_launch(void* const* d_in, const int* in_sizes, int n_in,
                              void* d_out, int out_size) {
    const float* x   = (const float*)d_in[0];
    const void*  ei  = d_in[1];
    const float* W1  = (const float*)d_in[2];
    const float* b1  = (const float*)d_in[3];
    const float* Wmu = (const float*)d_in[4];
    const float* bmu = (const float*)d_in[5];
    const float* Wls = (const float*)d_in[6];
    const float* bls = (const float*)d_in[7];
    float* out = (float*)d_out;

    const int E = in_sizes[1] / 2;

    const int nThr    = 256;
    const int nodeBlk = (NN + nThr - 1) / nThr;
    const int edgeBlk = (E + nThr - 1) / nThr;
    const int scanBlk = (NN + 1023) / 1024;   // 98
    const int propBlk = (int)(((long long)NN * 32 + nThr - 1) / nThr);
    const int gemmBlk = (NN + TMR - 1) / TMR;

    // dtype detection
    k_detect<<<1, 256>>>((const int*)ei);

    // CSR build + dinv (parallel 3-stage scan)
    k_zero_deg<<<nodeBlk, nThr>>>();
    k_deg<<<edgeBlk, nThr>>>(ei, E);
    k_scan_block<<<scanBlk, 1024>>>(NN);
    k_scan_top<<<1, 32>>>(scanBlk);
    k_finalize<<<nodeBlk, nThr>>>(NN, E);
    k_scatter<<<edgeBlk, nThr>>>(ei, E);

    // layer 1: GEMM (dinv-prescaled, fp16 out) -> prop (+bias+relu, fp16 out)
    k_gemm1<<<gemmBlk, nThr>>>(x, W1);
    k_prop1<<<propBlk, nThr>>>(b1);

    // shared propagation for mu/logstd (A linear: A(h@W) = (A h)@W)
    k_prop2<<<propBlk, nThr>>>();

    // dual output GEMM with bias
    k_gemm2<<<gemmBlk, nThr>>>(Wmu, bmu, Wls, bls, out);
}

// round 8
// speedup vs baseline: 3.9541x; 1.2333x over previous
#include <cuda_runtime.h>
#include <cuda_fp16.h>

#define NN    100000
#define EEMAX 4000000
#define INCH  256
#define HID   128
#define OUTC  64
#define FULLMASK 0xffffffffu

// -------- scratch (device globals; referenced ONLY from device code) --------
__device__ __half g_X16[(size_t)NN * INCH];   // fp16 copy of X
__device__ __half g_W16[(size_t)INCH * HID];  // fp16 copy of W1
__device__ __half g_H16a[(size_t)NN * HID];   // gemm1 out (prescaled, fp16)
__device__ __half g_H16b[(size_t)NN * HID];   // prop1 out (prescaled, fp16)
__device__ float  g_B1[(size_t)NN * HID];     // prop2 out (fp32, feeds gemm2)
__device__ float  g_dinv[NN];
__device__ int    g_deg[NN];
__device__ int    g_rowptr[NN + 1];
__device__ int    g_cursor[NN];
__device__ int    g_csr[EEMAX];
__device__ int    g_partial[128];
__device__ int    g_idx64;

// ---------------------------------------------------------------------------
// helpers
// ---------------------------------------------------------------------------
__device__ __forceinline__ float4 h4_to_f4(uint2 u) {
    __half2 h0 = *reinterpret_cast<__half2*>(&u.x);
    __half2 h1 = *reinterpret_cast<__half2*>(&u.y);
    float2 f0 = __half22float2(h0);
    float2 f1 = __half22float2(h1);
    return make_float4(f0.x, f0.y, f1.x, f1.y);
}

__device__ __forceinline__ uint2 f4_to_h4(float4 v) {
    __half2 h0 = __floats2half2_rn(v.x, v.y);
    __half2 h1 = __floats2half2_rn(v.z, v.w);
    uint2 u;
    u.x = *reinterpret_cast<unsigned*>(&h0);
    u.y = *reinterpret_cast<unsigned*>(&h1);
    return u;
}

__device__ __forceinline__ void ldsm_x4(unsigned& r0, unsigned& r1,
                                        unsigned& r2, unsigned& r3,
                                        unsigned addr) {
    asm volatile("ldmatrix.sync.aligned.m8n8.x4.shared.b16 {%0,%1,%2,%3}, [%4];"
                 : "=r"(r0), "=r"(r1), "=r"(r2), "=r"(r3) : "r"(addr));
}

__device__ __forceinline__ void ldsm_x4_t(unsigned& r0, unsigned& r1,
                                          unsigned& r2, unsigned& r3,
                                          unsigned addr) {
    asm volatile("ldmatrix.sync.aligned.m8n8.x4.trans.shared.b16 {%0,%1,%2,%3}, [%4];"
                 : "=r"(r0), "=r"(r1), "=r"(r2), "=r"(r3) : "r"(addr));
}

__device__ __forceinline__ void mma16816(float* c, const unsigned* a, const unsigned* b) {
    asm volatile(
        "mma.sync.aligned.m16n8k16.row.col.f32.f16.f16.f32 "
        "{%0,%1,%2,%3}, {%4,%5,%6,%7}, {%8,%9}, {%0,%1,%2,%3};"
        : "+f"(c[0]), "+f"(c[1]), "+f"(c[2]), "+f"(c[3])
        : "r"(a[0]), "r"(a[1]), "r"(a[2]), "r"(a[3]), "r"(b[0]), "r"(b[1]));
}

// ---------------------------------------------------------------------------
// fp32 -> fp16 conversion kernels (write device globals directly)
// ---------------------------------------------------------------------------
__global__ void k_cvtX(const float* __restrict__ x) {
    int i = blockIdx.x * blockDim.x + threadIdx.x;          // float4 index
    if (i < NN * INCH / 4)
        ((uint2*)g_X16)[i] = f4_to_h4(((const float4*)x)[i]);
}

__global__ void k_cvtW(const float* __restrict__ w) {
    int i = blockIdx.x * blockDim.x + threadIdx.x;
    if (i < INCH * HID / 4)
        ((uint2*)g_W16)[i] = f4_to_h4(((const float4*)w)[i]);
}

// ---------------------------------------------------------------------------
// edge_index dtype detection (int64 vs int32)
// ---------------------------------------------------------------------------
__global__ void k_detect(const int* __restrict__ ei32) {
    __shared__ int nz;
    if (threadIdx.x == 0) nz = 0;
    __syncthreads();
    int local = 0;
    for (int i = threadIdx.x; i < 4096; i += blockDim.x)
        if (ei32[2 * i + 1] != 0) local = 1;
    if (local) atomicOr(&nz, 1);
    __syncthreads();
    if (threadIdx.x == 0) g_idx64 = (nz == 0) ? 1 : 0;
}

__device__ __forceinline__ int load_idx(const void* ei, long long pos) {
    if (g_idx64) return (int)((const long long*)ei)[pos];
    return ((const int*)ei)[pos];
}

// ---------------------------------------------------------------------------
// CSR construction
// ---------------------------------------------------------------------------
__global__ void k_zero_deg() {
    int i = blockIdx.x * blockDim.x + threadIdx.x;
    if (i < NN) g_deg[i] = 0;
}

__global__ void k_deg(const void* __restrict__ ei, int e) {
    int i = blockIdx.x * blockDim.x + threadIdx.x;
    if (i < e) atomicAdd(&g_deg[load_idx(ei, (long long)e + i)], 1);
}

__global__ __launch_bounds__(1024) void k_scan_block(int n) {
    __shared__ int s[1024];
    int t = threadIdx.x;
    int i = blockIdx.x * 1024 + t;
    int v = (i < n) ? g_deg[i] : 0;
    s[t] = v;
    __syncthreads();
#pragma unroll
    for (int off = 1; off < 1024; off <<= 1) {
        int x = (t >= off) ? s[t - off] : 0;
        __syncthreads();
        s[t] += x;
        __syncthreads();
    }
    if (i < n) g_rowptr[i] = s[t] - v;
    if (t == 1023) g_partial[blockIdx.x] = s[1023];
}

__global__ void k_scan_top(int nblk) {
    if (threadIdx.x == 0) {
        int run = 0;
        for (int i = 0; i < nblk; i++) {
            int x = g_partial[i];
            g_partial[i] = run;
            run += x;
        }
    }
}

__global__ void k_finalize(int n, int e) {
    int i = blockIdx.x * blockDim.x + threadIdx.x;
    if (i < n) {
        int r = g_rowptr[i] + g_partial[i >> 10];
        g_rowptr[i] = r;
        g_cursor[i] = r;
        g_dinv[i]   = rsqrtf((float)g_deg[i] + 1.0f);
        if (i == 0) g_rowptr[n] = e;
    }
}

__global__ void k_scatter(const void* __restrict__ ei, int e) {
    int i = blockIdx.x * blockDim.x + threadIdx.x;
    if (i < e) {
        int s = load_idx(ei, i);
        int d = load_idx(ei, (long long)e + i);
        int pos = atomicAdd(&g_cursor[d], 1);
        g_csr[pos] = s;
    }
}

// ---------------------------------------------------------------------------
// GEMM1 (tensor core): g_H16a = fp16( (X16 @ W16) * dinv[row] )
// 128x128 tile, 8 warps (4M x 2N), mma.m16n8k16, fp32 accumulate.
// A smem [128][40] (pad 8), B smem [32][136] (pad 8): conflict-free ldmatrix.
// ---------------------------------------------------------------------------
#define A_LD 40
#define B_LD 136

__global__ __launch_bounds__(256) void k_gemm1h() {
    __shared__ __half As[128 * A_LD];
    __shared__ __half Bs[32 * B_LD];

    int t = threadIdx.x;
    int lane = t & 31;
    int w = t >> 5;
    int wm = w & 3;          // 0..3 -> M quarter (32 rows)
    int wn = w >> 2;         // 0..1 -> N half   (64 cols)
    int row0 = blockIdx.x * 128;

    // staging ids
    int arow = t >> 1, acol = (t & 1) * 16;   // A: 128 rows x 32 halves
    int brow = t >> 3, bcol = (t & 7) * 16;   // B: 32 rows x 128 halves
    int gr_a = row0 + arow;

    float c[2][8][4];
#pragma unroll
    for (int mi = 0; mi < 2; mi++)
#pragma unroll
        for (int ni = 0; ni < 8; ni++)
#pragma unroll
            for (int q = 0; q < 4; q++) c[mi][ni][q] = 0.f;

    unsigned as_base = (unsigned)__cvta_generic_to_shared(As);
    unsigned bs_base = (unsigned)__cvta_generic_to_shared(Bs);

    for (int k0 = 0; k0 < INCH; k0 += 32) {
        // stage A tile (rows row0..row0+127, k k0..k0+31)
        {
            uint4 z = make_uint4(0, 0, 0, 0);
            uint4 v0 = z, v1 = z;
            if (gr_a < NN) {
                const uint4* p = (const uint4*)(g_X16 + (long long)gr_a * INCH + k0 + acol);
                v0 = p[0];
                v1 = p[1];
            }
            uint4* d = (uint4*)(As + arow * A_LD + acol);
            d[0] = v0;
            d[1] = v1;
        }
        // stage B tile (k k0..k0+31, all 128 cols)
        {
            const uint4* p = (const uint4*)(g_W16 + (long long)(k0 + brow) * HID + bcol);
            uint4* d = (uint4*)(Bs + brow * B_LD + bcol);
            d[0] = p[0];
            d[1] = p[1];
        }
        __syncthreads();

#pragma unroll
        for (int ks = 0; ks < 32; ks += 16) {
            unsigned a[2][4];
#pragma unroll
            for (int mi = 0; mi < 2; mi++) {
                int m = wm * 32 + mi * 16 + (lane & 15);
                unsigned addr = as_base + (m * A_LD + ks + (lane >> 4) * 8) * 2;
                ldsm_x4(a[mi][0], a[mi][1], a[mi][2], a[mi][3], addr);
            }
            unsigned b[8][2];
#pragma unroll
            for (int nb = 0; nb < 4; nb++) {
                int n0 = wn * 64 + nb * 16;
                unsigned addr = bs_base + ((ks + (lane & 15)) * B_LD + n0 + (lane >> 4) * 8) * 2;
                unsigned r0, r1, r2, r3;
                ldsm_x4_t(r0, r1, r2, r3, addr);
                b[2 * nb][0] = r0;     b[2 * nb][1] = r1;
                b[2 * nb + 1][0] = r2; b[2 * nb + 1][1] = r3;
            }
#pragma unroll
            for (int mi = 0; mi < 2; mi++)
#pragma unroll
                for (int ni = 0; ni < 8; ni++)
                    mma16816(c[mi][ni], a[mi], b[ni]);
        }
        __syncthreads();
    }

    // epilogue: scale by dinv, store fp16
#pragma unroll
    for (int mi = 0; mi < 2; mi++) {
        int row_a = row0 + wm * 32 + mi * 16 + (lane >> 2);
        int row_b = row_a + 8;
        float sa = (row_a < NN) ? g_dinv[row_a] : 0.f;
        float sb = (row_b < NN) ? g_dinv[row_b] : 0.f;
#pragma unroll
        for (int ni = 0; ni < 8; ni++) {
            int col = wn * 64 + ni * 8 + (lane & 3) * 2;
            if (row_a < NN) {
                __half2 h = __floats2half2_rn(c[mi][ni][0] * sa, c[mi][ni][1] * sa);
                *(__half2*)(g_H16a + (long long)row_a * HID + col) = h;
            }
            if (row_b < NN) {
                __half2 h = __floats2half2_rn(c[mi][ni][2] * sb, c[mi][ni][3] * sb);
                *(__half2*)(g_H16a + (long long)row_b * HID + col) = h;
            }
        }
    }
}

// ---------------------------------------------------------------------------
// CSR propagation (fp16 gather, fp32 accumulate): warp per node.
// ---------------------------------------------------------------------------
__device__ __forceinline__ void prop_body_h(const __half* __restrict__ in,
                                            __half* __restrict__ outh,
                                            float* __restrict__ outf,
                                            const float* __restrict__ bias,
                                            int mode) {
    int node = (int)((blockIdx.x * (long long)blockDim.x + threadIdx.x) >> 5);
    int lane = threadIdx.x & 31;
    if (node >= NN) return;

    const uint2* IN = (const uint2*)in;
    int beg = g_rowptr[node];
    int end = g_rowptr[node + 1];

    float4 acc = h4_to_f4(IN[(long long)node * 32 + lane]);  // self-loop (pre-scaled)

    int e = beg;
    for (; e + 8 <= end; e += 8) {
        int s0 = g_csr[e];
        int s1 = g_csr[e + 1];
        int s2 = g_csr[e + 2];
        int s3 = g_csr[e + 3];
        int s4 = g_csr[e + 4];
        int s5 = g_csr[e + 5];
        int s6 = g_csr[e + 6];
        int s7 = g_csr[e + 7];
        uint2 u0 = IN[(long long)s0 * 32 + lane];
        uint2 u1 = IN[(long long)s1 * 32 + lane];
        uint2 u2 = IN[(long long)s2 * 32 + lane];
        uint2 u3 = IN[(long long)s3 * 32 + lane];
        uint2 u4 = IN[(long long)s4 * 32 + lane];
        uint2 u5 = IN[(long long)s5 * 32 + lane];
        uint2 u6 = IN[(long long)s6 * 32 + lane];
        uint2 u7 = IN[(long long)s7 * 32 + lane];
        float4 v0 = h4_to_f4(u0), v1 = h4_to_f4(u1), v2 = h4_to_f4(u2), v3 = h4_to_f4(u3);
        float4 v4 = h4_to_f4(u4), v5 = h4_to_f4(u5), v6 = h4_to_f4(u6), v7 = h4_to_f4(u7);
        acc.x += ((v0.x + v1.x) + (v2.x + v3.x)) + ((v4.x + v5.x) + (v6.x + v7.x));
        acc.y += ((v0.y + v1.y) + (v2.y + v3.y)) + ((v4.y + v5.y) + (v6.y + v7.y));
        acc.z += ((v0.z + v1.z) + (v2.z + v3.z)) + ((v4.z + v5.z) + (v6.z + v7.z));
        acc.w += ((v0.w + v1.w) + (v2.w + v3.w)) + ((v4.w + v5.w) + (v6.w + v7.w));
    }
    for (; e + 4 <= end; e += 4) {
        int s0 = g_csr[e];
        int s1 = g_csr[e + 1];
        int s2 = g_csr[e + 2];
        int s3 = g_csr[e + 3];
        float4 v0 = h4_to_f4(IN[(long long)s0 * 32 + lane]);
        float4 v1 = h4_to_f4(IN[(long long)s1 * 32 + lane]);
        float4 v2 = h4_to_f4(IN[(long long)s2 * 32 + lane]);
        float4 v3 = h4_to_f4(IN[(long long)s3 * 32 + lane]);
        acc.x += (v0.x + v1.x) + (v2.x + v3.x);
        acc.y += (v0.y + v1.y) + (v2.y + v3.y);
        acc.z += (v0.z + v1.z) + (v2.z + v3.z);
        acc.w += (v0.w + v1.w) + (v2.w + v3.w);
    }
    for (; e < end; e++) {
        int s = g_csr[e];
        float4 v = h4_to_f4(IN[(long long)s * 32 + lane]);
        acc.x += v.x; acc.y += v.y; acc.z += v.z; acc.w += v.w;
    }

    float dn = g_dinv[node];
    acc.x *= dn; acc.y *= dn; acc.z *= dn; acc.w *= dn;
    if (mode == 1) {
        float4 b = ((const float4*)bias)[lane];
        acc.x = fmaxf(acc.x + b.x, 0.f) * dn;
        acc.y = fmaxf(acc.y + b.y, 0.f) * dn;
        acc.z = fmaxf(acc.z + b.z, 0.f) * dn;
        acc.w = fmaxf(acc.w + b.w, 0.f) * dn;
        ((uint2*)outh)[(long long)node * 32 + lane] = f4_to_h4(acc);
    } else {
        ((float4*)outf)[(long long)node * 32 + lane] = acc;
    }
}

__global__ __launch_bounds__(256) void k_prop1(const float* __restrict__ b1) {
    prop_body_h(g_H16a, g_H16b, (float*)0, b1, 1);
}

__global__ __launch_bounds__(256) void k_prop2() {
    prop_body_h(g_H16b, (__half*)0, g_B1, (const float*)0, 0);
}

// ---------------------------------------------------------------------------
// GEMM2 (fp32 SIMT, unchanged): [mu | ls] = g_B1 @ [Wmu | Wls] + bias
// ---------------------------------------------------------------------------
#define KT  16
#define TMR 128

__global__ __launch_bounds__(256, 2) void k_gemm2(const float* __restrict__ Wmu,
                                                  const float* __restrict__ bmu,
                                                  const float* __restrict__ Wls,
                                                  const float* __restrict__ bls,
                                                  float* __restrict__ out) {
    __shared__ float As[KT][TMR];
    __shared__ float Bs[KT][HID];
    int t = threadIdx.x;
    int row0 = blockIdx.x * TMR;

    int arow = t >> 1, akk = (t & 1) * 8;
    int gr_a = row0 + arow;
    int bkk = t >> 4, bc = (t & 15) * 8;

    int ty = t >> 4, tx = t & 15;
    int rA0 = ty * 4, rA1 = 64 + ty * 4;
    int cB0 = tx * 4, cB1 = 64 + tx * 4;

    float acc[8][8];
#pragma unroll
    for (int r = 0; r < 8; r++)
#pragma unroll
        for (int c = 0; c < 8; c++) acc[r][c] = 0.f;

    float4 ra0 = make_float4(0, 0, 0, 0), ra1 = ra0, rb0, rb1;
    if (gr_a < NN) {
        const float* p = g_B1 + (long long)gr_a * HID + akk;
        ra0 = *(const float4*)p;
        ra1 = *(const float4*)(p + 4);
    }
    {
        const float* p = (bc < 64) ? (Wmu + (long long)bkk * OUTC + bc)
                                   : (Wls + (long long)bkk * OUTC + (bc - 64));
        rb0 = *(const float4*)p;
        rb1 = *(const float4*)(p + 4);
    }

    for (int k0 = 0; k0 < HID; k0 += KT) {
        As[akk + 0][arow] = ra0.x; As[akk + 1][arow] = ra0.y;
        As[akk + 2][arow] = ra0.z; As[akk + 3][arow] = ra0.w;
        As[akk + 4][arow] = ra1.x; As[akk + 5][arow] = ra1.y;
        As[akk + 6][arow] = ra1.z; As[akk + 7][arow] = ra1.w;
        *(float4*)&Bs[bkk][bc]     = rb0;
        *(float4*)&Bs[bkk][bc + 4] = rb1;
        __syncthreads();

        int kn = k0 + KT;
        if (kn < HID) {
            if (gr_a < NN) {
                const float* p = g_B1 + (long long)gr_a * HID + kn + akk;
                ra0 = *(const float4*)p;
                ra1 = *(const float4*)(p + 4);
            }
            const float* p = (bc < 64) ? (Wmu + (long long)(kn + bkk) * OUTC + bc)
                                       : (Wls + (long long)(kn + bkk) * OUTC + (bc - 64));
            rb0 = *(const float4*)p;
            rb1 = *(const float4*)(p + 4);
        }

#pragma unroll
        for (int kk = 0; kk < KT; kk++) {
            float4 a0 = *(const float4*)&As[kk][rA0];
            float4 a1 = *(const float4*)&As[kk][rA1];
            float4 b0 = *(const float4*)&Bs[kk][cB0];
            float4 b1 = *(const float4*)&Bs[kk][cB1];
            float av[8] = {a0.x, a0.y, a0.z, a0.w, a1.x, a1.y, a1.z, a1.w};
            float bv[8] = {b0.x, b0.y, b0.z, b0.w, b1.x, b1.y, b1.z, b1.w};
#pragma unroll
            for (int r = 0; r < 8; r++)
#pragma unroll
                for (int c = 0; c < 8; c++)
                    acc[r][c] = fmaf(av[r], bv[c], acc[r][c]);
        }
        __syncthreads();
    }

    float4 bv0 = *(const float4*)(bmu + cB0);
    float4 bv1 = *(const float4*)(bls + (cB1 - 64));
#pragma unroll
    for (int r = 0; r < 8; r++) {
        int gr = row0 + ((r < 4) ? (rA0 + r) : (rA1 + r - 4));
        if (gr < NN) {
            float4 v0 = make_float4(acc[r][0] + bv0.x, acc[r][1] + bv0.y,
                                    acc[r][2] + bv0.z, acc[r][3] + bv0.w);
            float4 v1 = make_float4(acc[r][4] + bv1.x, acc[r][5] + bv1.y,
                                    acc[r][6] + bv1.z, acc[r][7] + bv1.w);
            *(float4*)(out + (long long)gr * OUTC + cB0) = v0;
            *(float4*)(out + (long long)NN * OUTC + (long long)gr * OUTC + (cB1 - 64)) = v1;
        }
    }
}

// ---------------------------------------------------------------------------
extern "C" void kernel_launch(void* const* d_in, const int* in_sizes, int n_in,
                              void* d_out, int out_size) {
    const float* x   = (const float*)d_in[0];
    const void*  ei  = d_in[1];
    const float* W1  = (const float*)d_in[2];
    const float* b1  = (const float*)d_in[3];
    const float* Wmu = (const float*)d_in[4];
    const float* bmu = (const float*)d_in[5];
    const float* Wls = (const float*)d_in[6];
    const float* bls = (const float*)d_in[7];
    float* out = (float*)d_out;

    const int E = in_sizes[1] / 2;

    const int nThr    = 256;
    const int nodeBlk = (NN + nThr - 1) / nThr;
    const int edgeBlk = (E + nThr - 1) / nThr;
    const int scanBlk = (NN + 1023) / 1024;   // 98
    const int propBlk = (int)(((long long)NN * 32 + nThr - 1) / nThr);
    const int gemmBlk = (NN + TMR - 1) / TMR;
    const int cvtXBlk = (NN * INCH / 4 + nThr - 1) / nThr;
    const int cvtWBlk = (INCH * HID / 4 + nThr - 1) / nThr;

    // dtype detection + fp16 conversions
    k_detect<<<1, 256>>>((const int*)ei);
    k_cvtX<<<cvtXBlk, nThr>>>(x);
    k_cvtW<<<cvtWBlk, nThr>>>(W1);

    // CSR build + dinv (parallel 3-stage scan)
    k_zero_deg<<<nodeBlk, nThr>>>();
    k_deg<<<edgeBlk, nThr>>>(ei, E);
    k_scan_block<<<scanBlk, 1024>>>(NN);
    k_scan_top<<<1, 32>>>(scanBlk);
    k_finalize<<<nodeBlk, nThr>>>(NN, E);
    k_scatter<<<edgeBlk, nThr>>>(ei, E);

    // layer 1: tensor-core GEMM (dinv-prescaled fp16 out) -> prop
    k_gemm1h<<<gemmBlk, nThr>>>();
    k_prop1<<<propBlk, nThr>>>(b1);

    // shared propagation for mu/logstd (A linear: A(h@W) = (A h)@W)
    k_prop2<<<propBlk, nThr>>>();

    // dual output GEMM with bias
    k_gemm2<<<gemmBlk, nThr>>>(Wmu, bmu, Wls, bls, out);
}

// round 10
// speedup vs baseline: 4.9412x; 1.2497x over previous
#include <cuda_runtime.h>
#include <cuda_fp16.h>

#define NN    100000
#define EEMAX 4000000
#define INCH  256
#define HID   128
#define OUTC  64
#define FULLMASK 0xffffffffu

// -------- scratch (device globals; referenced ONLY from device code) --------
__device__ __half g_W16[(size_t)INCH * HID];  // fp16 W1
__device__ __half g_W2[(size_t)HID * 128];    // fp16 [Wmu | Wls] packed
__device__ __half g_H16a[(size_t)NN * HID];   // gemm1 out (prescaled, fp16)
__device__ __half g_H16b[(size_t)NN * HID];   // prop1 out (prescaled, fp16)
__device__ __half g_H16c[(size_t)NN * HID];   // prop2 out (fp16, feeds gemm2)
__device__ float  g_dinv[NN];
__device__ int    g_deg[NN];
__device__ int    g_rowptr[NN + 1];
__device__ int    g_cursor[NN];
__device__ int    g_csr[EEMAX];
__device__ int    g_partial[128];
__device__ int    g_idx64;

// ---------------------------------------------------------------------------
// helpers
// ---------------------------------------------------------------------------
__device__ __forceinline__ float4 h4_to_f4(uint2 u) {
    __half2 h0 = *reinterpret_cast<__half2*>(&u.x);
    __half2 h1 = *reinterpret_cast<__half2*>(&u.y);
    float2 f0 = __half22float2(h0);
    float2 f1 = __half22float2(h1);
    return make_float4(f0.x, f0.y, f1.x, f1.y);
}

__device__ __forceinline__ uint2 f4_to_h4(float4 v) {
    __half2 h0 = __floats2half2_rn(v.x, v.y);
    __half2 h1 = __floats2half2_rn(v.z, v.w);
    uint2 u;
    u.x = *reinterpret_cast<unsigned*>(&h0);
    u.y = *reinterpret_cast<unsigned*>(&h1);
    return u;
}

__device__ __forceinline__ void ldsm_x4(unsigned& r0, unsigned& r1,
                                        unsigned& r2, unsigned& r3,
                                        unsigned addr) {
    asm volatile("ldmatrix.sync.aligned.m8n8.x4.shared.b16 {%0,%1,%2,%3}, [%4];"
                 : "=r"(r0), "=r"(r1), "=r"(r2), "=r"(r3) : "r"(addr));
}

__device__ __forceinline__ void ldsm_x4_t(unsigned& r0, unsigned& r1,
                                          unsigned& r2, unsigned& r3,
                                          unsigned addr) {
    asm volatile("ldmatrix.sync.aligned.m8n8.x4.trans.shared.b16 {%0,%1,%2,%3}, [%4];"
                 : "=r"(r0), "=r"(r1), "=r"(r2), "=r"(r3) : "r"(addr));
}

__device__ __forceinline__ void mma16816(float* c, const unsigned* a, const unsigned* b) {
    asm volatile(
        "mma.sync.aligned.m16n8k16.row.col.f32.f16.f16.f32 "
        "{%0,%1,%2,%3}, {%4,%5,%6,%7}, {%8,%9}, {%0,%1,%2,%3};"
        : "+f"(c[0]), "+f"(c[1]), "+f"(c[2]), "+f"(c[3])
        : "r"(a[0]), "r"(a[1]), "r"(a[2]), "r"(a[3]), "r"(b[0]), "r"(b[1]));
}

// ---------------------------------------------------------------------------
// weight conversion kernels
// ---------------------------------------------------------------------------
__global__ void k_cvtW(const float* __restrict__ w) {
    int i = blockIdx.x * blockDim.x + threadIdx.x;
    if (i < INCH * HID / 4)
        ((uint2*)g_W16)[i] = f4_to_h4(((const float4*)w)[i]);
}

// pack [Wmu | Wls] -> g_W2[k][c]: c<64 from Wmu[k][c], else Wls[k][c-64]
__global__ void k_cvtW2(const float* __restrict__ wmu, const float* __restrict__ wls) {
    int i = blockIdx.x * blockDim.x + threadIdx.x;   // element index over 128*128
    if (i < HID * 128) {
        int k = i >> 7, c = i & 127;
        float v = (c < 64) ? wmu[k * OUTC + c] : wls[k * OUTC + (c - 64)];
        g_W2[i] = __float2half_rn(v);
    }
}

// ---------------------------------------------------------------------------
// edge_index dtype detection (int64 vs int32)
// ---------------------------------------------------------------------------
__global__ void k_detect(const int* __restrict__ ei32) {
    __shared__ int nz;
    if (threadIdx.x == 0) nz = 0;
    __syncthreads();
    int local = 0;
    for (int i = threadIdx.x; i < 4096; i += blockDim.x)
        if (ei32[2 * i + 1] != 0) local = 1;
    if (local) atomicOr(&nz, 1);
    __syncthreads();
    if (threadIdx.x == 0) g_idx64 = (nz == 0) ? 1 : 0;
}

__device__ __forceinline__ int load_idx(const void* ei, long long pos) {
    if (g_idx64) return (int)((const long long*)ei)[pos];
    return ((const int*)ei)[pos];
}

// ---------------------------------------------------------------------------
// CSR construction
// ---------------------------------------------------------------------------
__global__ void k_zero_deg() {
    int i = blockIdx.x * blockDim.x + threadIdx.x;
    if (i < NN) g_deg[i] = 0;
}

__global__ void k_deg(const void* __restrict__ ei, int e) {
    int i = blockIdx.x * blockDim.x + threadIdx.x;
    if (i < e) atomicAdd(&g_deg[load_idx(ei, (long long)e + i)], 1);
}

__global__ __launch_bounds__(1024) void k_scan_block(int n) {
    __shared__ int s[1024];
    int t = threadIdx.x;
    int i = blockIdx.x * 1024 + t;
    int v = (i < n) ? g_deg[i] : 0;
    s[t] = v;
    __syncthreads();
#pragma unroll
    for (int off = 1; off < 1024; off <<= 1) {
        int x = (t >= off) ? s[t - off] : 0;
        __syncthreads();
        s[t] += x;
        __syncthreads();
    }
    if (i < n) g_rowptr[i] = s[t] - v;
    if (t == 1023) g_partial[blockIdx.x] = s[1023];
}

__global__ void k_scan_top(int nblk) {
    if (threadIdx.x == 0) {
        int run = 0;
        for (int i = 0; i < nblk; i++) {
            int x = g_partial[i];
            g_partial[i] = run;
            run += x;
        }
    }
}

__global__ void k_finalize(int n, int e) {
    int i = blockIdx.x * blockDim.x + threadIdx.x;
    if (i < n) {
        int r = g_rowptr[i] + g_partial[i >> 10];
        g_rowptr[i] = r;
        g_cursor[i] = r;
        g_dinv[i]   = rsqrtf((float)g_deg[i] + 1.0f);
        if (i == 0) g_rowptr[n] = e;
    }
}

__global__ void k_scatter(const void* __restrict__ ei, int e) {
    int i = blockIdx.x * blockDim.x + threadIdx.x;
    if (i < e) {
        int s = load_idx(ei, i);
        int d = load_idx(ei, (long long)e + i);
        int pos = atomicAdd(&g_cursor[d], 1);
        g_csr[pos] = s;
    }
}

// ---------------------------------------------------------------------------
// GEMM1 (tensor core): g_H16a = fp16( (X @ W1) * dinv[row] )
// Reads fp32 X directly; converts to fp16 in registers while staging.
// 128x128 tile, 8 warps (4M x 2N), mma.m16n8k16, fp32 accumulate.
// ---------------------------------------------------------------------------
#define A_LD 40
#define B_LD 136

__global__ __launch_bounds__(256) void k_gemm1h(const float* __restrict__ X) {
    __shared__ __half As[128 * A_LD];
    __shared__ __half Bs[32 * B_LD];

    int t = threadIdx.x;
    int lane = t & 31;
    int w = t >> 5;
    int wm = w & 3;
    int wn = w >> 2;
    int row0 = blockIdx.x * 128;

    int arow = t >> 1, acol = (t & 1) * 16;   // A: 128 rows x 32 halves/kstep
    int brow = t >> 3, bcol = (t & 7) * 16;   // B: 32 rows x 128 halves
    int gr_a = row0 + arow;

    float c[2][8][4];
#pragma unroll
    for (int mi = 0; mi < 2; mi++)
#pragma unroll
        for (int ni = 0; ni < 8; ni++)
#pragma unroll
            for (int q = 0; q < 4; q++) c[mi][ni][q] = 0.f;

    unsigned as_base = (unsigned)__cvta_generic_to_shared(As);
    unsigned bs_base = (unsigned)__cvta_generic_to_shared(Bs);

    for (int k0 = 0; k0 < INCH; k0 += 32) {
        {   // stage A: 16 fp32 -> 16 fp16 per thread
            float4 z = make_float4(0, 0, 0, 0);
            float4 f0 = z, f1 = z, f2 = z, f3 = z;
            if (gr_a < NN) {
                const float4* p = (const float4*)(X + (long long)gr_a * INCH + k0 + acol);
                f0 = p[0]; f1 = p[1]; f2 = p[2]; f3 = p[3];
            }
            uint2 h0 = f4_to_h4(f0), h1 = f4_to_h4(f1);
            uint2 h2 = f4_to_h4(f2), h3 = f4_to_h4(f3);
            uint4* d = (uint4*)(As + arow * A_LD + acol);
            d[0] = make_uint4(h0.x, h0.y, h1.x, h1.y);
            d[1] = make_uint4(h2.x, h2.y, h3.x, h3.y);
        }
        {   // stage B tile
            const uint4* p = (const uint4*)(g_W16 + (long long)(k0 + brow) * HID + bcol);
            uint4* d = (uint4*)(Bs + brow * B_LD + bcol);
            d[0] = p[0];
            d[1] = p[1];
        }
        __syncthreads();

#pragma unroll
        for (int ks = 0; ks < 32; ks += 16) {
            unsigned a[2][4];
#pragma unroll
            for (int mi = 0; mi < 2; mi++) {
                int m = wm * 32 + mi * 16 + (lane & 15);
                unsigned addr = as_base + (m * A_LD + ks + (lane >> 4) * 8) * 2;
                ldsm_x4(a[mi][0], a[mi][1], a[mi][2], a[mi][3], addr);
            }
            unsigned b[8][2];
#pragma unroll
            for (int nb = 0; nb < 4; nb++) {
                int n0 = wn * 64 + nb * 16;
                unsigned addr = bs_base + ((ks + (lane & 15)) * B_LD + n0 + (lane >> 4) * 8) * 2;
                unsigned r0, r1, r2, r3;
                ldsm_x4_t(r0, r1, r2, r3, addr);
                b[2 * nb][0] = r0;     b[2 * nb][1] = r1;
                b[2 * nb + 1][0] = r2; b[2 * nb + 1][1] = r3;
            }
#pragma unroll
            for (int mi = 0; mi < 2; mi++)
#pragma unroll
                for (int ni = 0; ni < 8; ni++)
                    mma16816(c[mi][ni], a[mi], b[ni]);
        }
        __syncthreads();
    }

#pragma unroll
    for (int mi = 0; mi < 2; mi++) {
        int row_a = row0 + wm * 32 + mi * 16 + (lane >> 2);
        int row_b = row_a + 8;
        float sa = (row_a < NN) ? g_dinv[row_a] : 0.f;
        float sb = (row_b < NN) ? g_dinv[row_b] : 0.f;
#pragma unroll
        for (int ni = 0; ni < 8; ni++) {
            int col = wn * 64 + ni * 8 + (lane & 3) * 2;
            if (row_a < NN) {
                __half2 h = __floats2half2_rn(c[mi][ni][0] * sa, c[mi][ni][1] * sa);
                *(__half2*)(g_H16a + (long long)row_a * HID + col) = h;
            }
            if (row_b < NN) {
                __half2 h = __floats2half2_rn(c[mi][ni][2] * sb, c[mi][ni][3] * sb);
                *(__half2*)(g_H16a + (long long)row_b * HID + col) = h;
            }
        }
    }
}

// ---------------------------------------------------------------------------
// CSR propagation (fp16 gather, fp32 accumulate): warp per node.
// mode=1: fp16 out = h( dinv*relu(dn*sum + b1) )
// mode=2: fp16 out = h( dn*sum )
// ---------------------------------------------------------------------------
__device__ __forceinline__ void prop_body_h(const __half* __restrict__ in,
                                            __half* __restrict__ outh,
                                            const float* __restrict__ bias,
                                            int mode) {
    int node = (int)((blockIdx.x * (long long)blockDim.x + threadIdx.x) >> 5);
    int lane = threadIdx.x & 31;
    if (node >= NN) return;

    const uint2* IN = (const uint2*)in;
    int beg = g_rowptr[node];
    int end = g_rowptr[node + 1];

    float4 acc = h4_to_f4(IN[(long long)node * 32 + lane]);  // self-loop (pre-scaled)

    int e = beg;
    for (; e + 8 <= end; e += 8) {
        int s0 = g_csr[e];
        int s1 = g_csr[e + 1];
        int s2 = g_csr[e + 2];
        int s3 = g_csr[e + 3];
        int s4 = g_csr[e + 4];
        int s5 = g_csr[e + 5];
        int s6 = g_csr[e + 6];
        int s7 = g_csr[e + 7];
        uint2 u0 = IN[(long long)s0 * 32 + lane];
        uint2 u1 = IN[(long long)s1 * 32 + lane];
        uint2 u2 = IN[(long long)s2 * 32 + lane];
        uint2 u3 = IN[(long long)s3 * 32 + lane];
        uint2 u4 = IN[(long long)s4 * 32 + lane];
        uint2 u5 = IN[(long long)s5 * 32 + lane];
        uint2 u6 = IN[(long long)s6 * 32 + lane];
        uint2 u7 = IN[(long long)s7 * 32 + lane];
        float4 v0 = h4_to_f4(u0), v1 = h4_to_f4(u1), v2 = h4_to_f4(u2), v3 = h4_to_f4(u3);
        float4 v4 = h4_to_f4(u4), v5 = h4_to_f4(u5), v6 = h4_to_f4(u6), v7 = h4_to_f4(u7);
        acc.x += ((v0.x + v1.x) + (v2.x + v3.x)) + ((v4.x + v5.x) + (v6.x + v7.x));
        acc.y += ((v0.y + v1.y) + (v2.y + v3.y)) + ((v4.y + v5.y) + (v6.y + v7.y));
        acc.z += ((v0.z + v1.z) + (v2.z + v3.z)) + ((v4.z + v5.z) + (v6.z + v7.z));
        acc.w += ((v0.w + v1.w) + (v2.w + v3.w)) + ((v4.w + v5.w) + (v6.w + v7.w));
    }
    for (; e + 4 <= end; e += 4) {
        int s0 = g_csr[e];
        int s1 = g_csr[e + 1];
        int s2 = g_csr[e + 2];
        int s3 = g_csr[e + 3];
        float4 v0 = h4_to_f4(IN[(long long)s0 * 32 + lane]);
        float4 v1 = h4_to_f4(IN[(long long)s1 * 32 + lane]);
        float4 v2 = h4_to_f4(IN[(long long)s2 * 32 + lane]);
        float4 v3 = h4_to_f4(IN[(long long)s3 * 32 + lane]);
        acc.x += (v0.x + v1.x) + (v2.x + v3.x);
        acc.y += (v0.y + v1.y) + (v2.y + v3.y);
        acc.z += (v0.z + v1.z) + (v2.z + v3.z);
        acc.w += (v0.w + v1.w) + (v2.w + v3.w);
    }
    for (; e < end; e++) {
        int s = g_csr[e];
        float4 v = h4_to_f4(IN[(long long)s * 32 + lane]);
        acc.x += v.x; acc.y += v.y; acc.z += v.z; acc.w += v.w;
    }

    float dn = g_dinv[node];
    acc.x *= dn; acc.y *= dn; acc.z *= dn; acc.w *= dn;
    if (mode == 1) {
        float4 b = ((const float4*)bias)[lane];
        acc.x = fmaxf(acc.x + b.x, 0.f) * dn;
        acc.y = fmaxf(acc.y + b.y, 0.f) * dn;
        acc.z = fmaxf(acc.z + b.z, 0.f) * dn;
        acc.w = fmaxf(acc.w + b.w, 0.f) * dn;
    }
    ((uint2*)outh)[(long long)node * 32 + lane] = f4_to_h4(acc);
}

__global__ __launch_bounds__(256) void k_prop1(const float* __restrict__ b1) {
    prop_body_h(g_H16a, g_H16b, b1, 1);
}

__global__ __launch_bounds__(256) void k_prop2() {
    prop_body_h(g_H16b, g_H16c, (const float*)0, 2);
}

// ---------------------------------------------------------------------------
// GEMM2 (tensor core): [mu | ls] = g_H16c @ g_W2 + bias  (fp32 out)
// Same structure as gemm1h; K = 128. Warp's wn selects mu (0) / ls (1) half.
// ---------------------------------------------------------------------------
__global__ __launch_bounds__(256) void k_gemm2h(const float* __restrict__ bmu,
                                                const float* __restrict__ bls,
                                                float* __restrict__ out) {
    __shared__ __half As[128 * A_LD];
    __shared__ __half Bs[32 * B_LD];

    int t = threadIdx.x;
    int lane = t & 31;
    int w = t >> 5;
    int wm = w & 3;
    int wn = w >> 2;
    int row0 = blockIdx.x * 128;

    int arow = t >> 1, acol = (t & 1) * 16;
    int brow = t >> 3, bcol = (t & 7) * 16;
    int gr_a = row0 + arow;

    float c[2][8][4];
#pragma unroll
    for (int mi = 0; mi < 2; mi++)
#pragma unroll
        for (int ni = 0; ni < 8; ni++)
#pragma unroll
            for (int q = 0; q < 4; q++) c[mi][ni][q] = 0.f;

    unsigned as_base = (unsigned)__cvta_generic_to_shared(As);
    unsigned bs_base = (unsigned)__cvta_generic_to_shared(Bs);

    for (int k0 = 0; k0 < HID; k0 += 32) {
        {
            uint4 z = make_uint4(0, 0, 0, 0);
            uint4 v0 = z, v1 = z;
            if (gr_a < NN) {
                const uint4* p = (const uint4*)(g_H16c + (long long)gr_a * HID + k0 + acol);
                v0 = p[0];
                v1 = p[1];
            }
            uint4* d = (uint4*)(As + arow * A_LD + acol);
            d[0] = v0;
            d[1] = v1;
        }
        {
            const uint4* p = (const uint4*)(g_W2 + (long long)(k0 + brow) * 128 + bcol);
            uint4* d = (uint4*)(Bs + brow * B_LD + bcol);
            d[0] = p[0];
            d[1] = p[1];
        }
        __syncthreads();

#pragma unroll
        for (int ks = 0; ks < 32; ks += 16) {
            unsigned a[2][4];
#pragma unroll
            for (int mi = 0; mi < 2; mi++) {
                int m = wm * 32 + mi * 16 + (lane & 15);
                unsigned addr = as_base + (m * A_LD + ks + (lane >> 4) * 8) * 2;
                ldsm_x4(a[mi][0], a[mi][1], a[mi][2], a[mi][3], addr);
            }
            unsigned b[8][2];
#pragma unroll
            for (int nb = 0; nb < 4; nb++) {
                int n0 = wn * 64 + nb * 16;
                unsigned addr = bs_base + ((ks + (lane & 15)) * B_LD + n0 + (lane >> 4) * 8) * 2;
                unsigned r0, r1, r2, r3;
                ldsm_x4_t(r0, r1, r2, r3, addr);
                b[2 * nb][0] = r0;     b[2 * nb][1] = r1;
                b[2 * nb + 1][0] = r2; b[2 * nb + 1][1] = r3;
            }
#pragma unroll
            for (int mi = 0; mi < 2; mi++)
#pragma unroll
                for (int ni = 0; ni < 8; ni++)
                    mma16816(c[mi][ni], a[mi], b[ni]);
        }
        __syncthreads();
    }

    // epilogue: wn=0 -> mu (out), wn=1 -> ls (out + NN*OUTC)
    const float* bias = (wn == 0) ? bmu : bls;
    float* base = (wn == 0) ? out : (out + (long long)NN * OUTC);
#pragma unroll
    for (int mi = 0; mi < 2; mi++) {
        int row_a = row0 + wm * 32 + mi * 16 + (lane >> 2);
        int row_b = row_a + 8;
#pragma unroll
        for (int ni = 0; ni < 8; ni++) {
            int cc = ni * 8 + (lane & 3) * 2;   // 0..63 within the half
            float b0 = bias[cc], b1v = bias[cc + 1];
            if (row_a < NN) {
                float2 v = make_float2(c[mi][ni][0] + b0, c[mi][ni][1] + b1v);
                *(float2*)(base + (long long)row_a * OUTC + cc) = v;
            }
            if (row_b < NN) {
                float2 v = make_float2(c[mi][ni][2] + b0, c[mi][ni][3] + b1v);
                *(float2*)(base + (long long)row_b * OUTC + cc) = v;
            }
        }
    }
}

// ---------------------------------------------------------------------------
extern "C" void kernel_launch(void* const* d_in, const int* in_sizes, int n_in,
                              void* d_out, int out_size) {
    const float* x   = (const float*)d_in[0];
    const void*  ei  = d_in[1];
    const float* W1  = (const float*)d_in[2];
    const float* b1  = (const float*)d_in[3];
    const float* Wmu = (const float*)d_in[4];
    const float* bmu = (const float*)d_in[5];
    const float* Wls = (const float*)d_in[6];
    const float* bls = (const float*)d_in[7];
    float* out = (float*)d_out;

    const int E = in_sizes[1] / 2;

    const int nThr    = 256;
    const int nodeBlk = (NN + nThr - 1) / nThr;
    const int edgeBlk = (E + nThr - 1) / nThr;
    const int scanBlk = (NN + 1023) / 1024;   // 98
    const int propBlk = (int)(((long long)NN * 32 + nThr - 1) / nThr);
    const int gemmBlk = (NN + 127) / 128;
    const int cvtWBlk = (INCH * HID / 4 + nThr - 1) / nThr;
    const int cvtW2Blk = (HID * 128 + nThr - 1) / nThr;

    // dtype detection + weight conversions
    k_detect<<<1, 256>>>((const int*)ei);
    k_cvtW<<<cvtWBlk, nThr>>>(W1);
    k_cvtW2<<<cvtW2Blk, nThr>>>(Wmu, Wls);

    // CSR build + dinv (parallel 3-stage scan)
    k_zero_deg<<<nodeBlk, nThr>>>();
    k_deg<<<edgeBlk, nThr>>>(ei, E);
    k_scan_block<<<scanBlk, 1024>>>(NN);
    k_scan_top<<<1, 32>>>(scanBlk);
    k_finalize<<<nodeBlk, nThr>>>(NN, E);
    k_scatter<<<edgeBlk, nThr>>>(ei, E);

    // layer 1: tensor-core GEMM (fp32 X staged to fp16 in-kernel) -> prop
    k_gemm1h<<<gemmBlk, nThr>>>(x);
    k_prop1<<<propBlk, nThr>>>(b1);

    // shared propagation for mu/logstd (A linear: A(h@W) = (A h)@W)
    k_prop2<<<propBlk, nThr>>>();

    // dual output tensor-core GEMM with bias
    k_gemm2h<<<gemmBlk, nThr>>>(bmu, bls, out);
}

// round 11
// speedup vs baseline: 4.9795x; 1.0077x over previous
#include <cuda_runtime.h>
#include <cuda_fp16.h>

#define NN    100000
#define EEMAX 4000000
#define INCH  256
#define HID   128
#define OUTC  64
#define FULLMASK 0xffffffffu

// -------- scratch (device globals; referenced ONLY from device code) --------
__device__ __half g_W16[(size_t)INCH * HID];  // fp16 W1
__device__ __half g_W2[(size_t)HID * 128];    // fp16 [Wmu | Wls] packed
__device__ __half g_H16a[(size_t)NN * HID];   // gemm1 out (prescaled, fp16)
__device__ __half g_H16b[(size_t)NN * HID];   // prop1 out (prescaled, fp16)
__device__ __half g_H16c[(size_t)NN * HID];   // prop2 out (fp16, feeds gemm2)
__device__ float  g_dinv[NN];
__device__ int    g_deg[NN];
__device__ int    g_rowptr[NN + 1];
__device__ int    g_cursor[NN];
__device__ int    g_csr[EEMAX];
__device__ int    g_partial[128];
__device__ int    g_idx64;

// ---------------------------------------------------------------------------
// helpers
// ---------------------------------------------------------------------------
__device__ __forceinline__ float4 h4_to_f4(uint2 u) {
    __half2 h0 = *reinterpret_cast<__half2*>(&u.x);
    __half2 h1 = *reinterpret_cast<__half2*>(&u.y);
    float2 f0 = __half22float2(h0);
    float2 f1 = __half22float2(h1);
    return make_float4(f0.x, f0.y, f1.x, f1.y);
}

__device__ __forceinline__ uint2 f4_to_h4(float4 v) {
    __half2 h0 = __floats2half2_rn(v.x, v.y);
    __half2 h1 = __floats2half2_rn(v.z, v.w);
    uint2 u;
    u.x = *reinterpret_cast<unsigned*>(&h0);
    u.y = *reinterpret_cast<unsigned*>(&h1);
    return u;
}

__device__ __forceinline__ void ldsm_x4(unsigned& r0, unsigned& r1,
                                        unsigned& r2, unsigned& r3,
                                        unsigned addr) {
    asm volatile("ldmatrix.sync.aligned.m8n8.x4.shared.b16 {%0,%1,%2,%3}, [%4];"
                 : "=r"(r0), "=r"(r1), "=r"(r2), "=r"(r3) : "r"(addr));
}

__device__ __forceinline__ void ldsm_x4_t(unsigned& r0, unsigned& r1,
                                          unsigned& r2, unsigned& r3,
                                          unsigned addr) {
    asm volatile("ldmatrix.sync.aligned.m8n8.x4.trans.shared.b16 {%0,%1,%2,%3}, [%4];"
                 : "=r"(r0), "=r"(r1), "=r"(r2), "=r"(r3) : "r"(addr));
}

__device__ __forceinline__ void mma16816(float* c, const unsigned* a, const unsigned* b) {
    asm volatile(
        "mma.sync.aligned.m16n8k16.row.col.f32.f16.f16.f32 "
        "{%0,%1,%2,%3}, {%4,%5,%6,%7}, {%8,%9}, {%0,%1,%2,%3};"
        : "+f"(c[0]), "+f"(c[1]), "+f"(c[2]), "+f"(c[3])
        : "r"(a[0]), "r"(a[1]), "r"(a[2]), "r"(a[3]), "r"(b[0]), "r"(b[1]));
}

// ---------------------------------------------------------------------------
// weight conversion kernels
// ---------------------------------------------------------------------------
__global__ void k_cvtW(const float* __restrict__ w) {
    int i = blockIdx.x * blockDim.x + threadIdx.x;
    if (i < INCH * HID / 4)
        ((uint2*)g_W16)[i] = f4_to_h4(((const float4*)w)[i]);
}

// pack [Wmu | Wls] -> g_W2[k][c]: c<64 from Wmu[k][c], else Wls[k][c-64]
__global__ void k_cvtW2(const float* __restrict__ wmu, const float* __restrict__ wls) {
    int i = blockIdx.x * blockDim.x + threadIdx.x;   // element index over 128*128
    if (i < HID * 128) {
        int k = i >> 7, c = i & 127;
        float v = (c < 64) ? wmu[k * OUTC + c] : wls[k * OUTC + (c - 64)];
        g_W2[i] = __float2half_rn(v);
    }
}

// ---------------------------------------------------------------------------
// edge_index dtype detection (int64 vs int32)
// ---------------------------------------------------------------------------
__global__ void k_detect(const int* __restrict__ ei32) {
    __shared__ int nz;
    if (threadIdx.x == 0) nz = 0;
    __syncthreads();
    int local = 0;
    for (int i = threadIdx.x; i < 4096; i += blockDim.x)
        if (ei32[2 * i + 1] != 0) local = 1;
    if (local) atomicOr(&nz, 1);
    __syncthreads();
    if (threadIdx.x == 0) g_idx64 = (nz == 0) ? 1 : 0;
}

__device__ __forceinline__ int load_idx(const void* ei, long long pos) {
    if (g_idx64) return (int)((const long long*)ei)[pos];
    return ((const int*)ei)[pos];
}

// ---------------------------------------------------------------------------
// CSR construction
// ---------------------------------------------------------------------------
__global__ void k_zero_deg() {
    int i = blockIdx.x * blockDim.x + threadIdx.x;
    if (i < NN) g_deg[i] = 0;
}

__global__ void k_deg(const void* __restrict__ ei, int e) {
    int i = blockIdx.x * blockDim.x + threadIdx.x;
    if (i < e) atomicAdd(&g_deg[load_idx(ei, (long long)e + i)], 1);
}

__global__ __launch_bounds__(1024) void k_scan_block(int n) {
    __shared__ int s[1024];
    int t = threadIdx.x;
    int i = blockIdx.x * 1024 + t;
    int v = (i < n) ? g_deg[i] : 0;
    s[t] = v;
    __syncthreads();
#pragma unroll
    for (int off = 1; off < 1024; off <<= 1) {
        int x = (t >= off) ? s[t - off] : 0;
        __syncthreads();
        s[t] += x;
        __syncthreads();
    }
    if (i < n) g_rowptr[i] = s[t] - v;
    if (t == 1023) g_partial[blockIdx.x] = s[1023];
}

__global__ void k_scan_top(int nblk) {
    if (threadIdx.x == 0) {
        int run = 0;
        for (int i = 0; i < nblk; i++) {
            int x = g_partial[i];
            g_partial[i] = run;
            run += x;
        }
    }
}

__global__ void k_finalize(int n, int e) {
    int i = blockIdx.x * blockDim.x + threadIdx.x;
    if (i < n) {
        int r = g_rowptr[i] + g_partial[i >> 10];
        g_rowptr[i] = r;
        g_cursor[i] = r;
        g_dinv[i]   = rsqrtf((float)g_deg[i] + 1.0f);
        if (i == 0) g_rowptr[n] = e;
    }
}

__global__ void k_scatter(const void* __restrict__ ei, int e) {
    int i = blockIdx.x * blockDim.x + threadIdx.x;
    if (i < e) {
        int s = load_idx(ei, i);
        int d = load_idx(ei, (long long)e + i);
        int pos = atomicAdd(&g_cursor[d], 1);
        g_csr[pos] = s;
    }
}

// ---------------------------------------------------------------------------
// GEMM1 (tensor core): g_H16a = fp16( (X @ W1) * dinv[row] )
// Reads fp32 X directly; converts to fp16 in registers while staging.
// 128x128 tile, 8 warps (4M x 2N), mma.m16n8k16, fp32 accumulate.
// ---------------------------------------------------------------------------
#define A_LD 40
#define B_LD 136

__global__ __launch_bounds__(256) void k_gemm1h(const float* __restrict__ X) {
    __shared__ __half As[128 * A_LD];
    __shared__ __half Bs[32 * B_LD];

    int t = threadIdx.x;
    int lane = t & 31;
    int w = t >> 5;
    int wm = w & 3;
    int wn = w >> 2;
    int row0 = blockIdx.x * 128;

    int arow = t >> 1, acol = (t & 1) * 16;   // A: 128 rows x 32 halves/kstep
    int brow = t >> 3, bcol = (t & 7) * 16;   // B: 32 rows x 128 halves
    int gr_a = row0 + arow;

    float c[2][8][4];
#pragma unroll
    for (int mi = 0; mi < 2; mi++)
#pragma unroll
        for (int ni = 0; ni < 8; ni++)
#pragma unroll
            for (int q = 0; q < 4; q++) c[mi][ni][q] = 0.f;

    unsigned as_base = (unsigned)__cvta_generic_to_shared(As);
    unsigned bs_base = (unsigned)__cvta_generic_to_shared(Bs);

    for (int k0 = 0; k0 < INCH; k0 += 32) {
        {   // stage A: 16 fp32 -> 16 fp16 per thread
            float4 z = make_float4(0, 0, 0, 0);
            float4 f0 = z, f1 = z, f2 = z, f3 = z;
            if (gr_a < NN) {
                const float4* p = (const float4*)(X + (long long)gr_a * INCH + k0 + acol);
                f0 = p[0]; f1 = p[1]; f2 = p[2]; f3 = p[3];
            }
            uint2 h0 = f4_to_h4(f0), h1 = f4_to_h4(f1);
            uint2 h2 = f4_to_h4(f2), h3 = f4_to_h4(f3);
            uint4* d = (uint4*)(As + arow * A_LD + acol);
            d[0] = make_uint4(h0.x, h0.y, h1.x, h1.y);
            d[1] = make_uint4(h2.x, h2.y, h3.x, h3.y);
        }
        {   // stage B tile
            const uint4* p = (const uint4*)(g_W16 + (long long)(k0 + brow) * HID + bcol);
            uint4* d = (uint4*)(Bs + brow * B_LD + bcol);
            d[0] = p[0];
            d[1] = p[1];
        }
        __syncthreads();

#pragma unroll
        for (int ks = 0; ks < 32; ks += 16) {
            unsigned a[2][4];
#pragma unroll
            for (int mi = 0; mi < 2; mi++) {
                int m = wm * 32 + mi * 16 + (lane & 15);
                unsigned addr = as_base + (m * A_LD + ks + (lane >> 4) * 8) * 2;
                ldsm_x4(a[mi][0], a[mi][1], a[mi][2], a[mi][3], addr);
            }
            unsigned b[8][2];
#pragma unroll
            for (int nb = 0; nb < 4; nb++) {
                int n0 = wn * 64 + nb * 16;
                unsigned addr = bs_base + ((ks + (lane & 15)) * B_LD + n0 + (lane >> 4) * 8) * 2;
                unsigned r0, r1, r2, r3;
                ldsm_x4_t(r0, r1, r2, r3, addr);
                b[2 * nb][0] = r0;     b[2 * nb][1] = r1;
                b[2 * nb + 1][0] = r2; b[2 * nb + 1][1] = r3;
            }
#pragma unroll
            for (int mi = 0; mi < 2; mi++)
#pragma unroll
                for (int ni = 0; ni < 8; ni++)
                    mma16816(c[mi][ni], a[mi], b[ni]);
        }
        __syncthreads();
    }

#pragma unroll
    for (int mi = 0; mi < 2; mi++) {
        int row_a = row0 + wm * 32 + mi * 16 + (lane >> 2);
        int row_b = row_a + 8;
        float sa = (row_a < NN) ? g_dinv[row_a] : 0.f;
        float sb = (row_b < NN) ? g_dinv[row_b] : 0.f;
#pragma unroll
        for (int ni = 0; ni < 8; ni++) {
            int col = wn * 64 + ni * 8 + (lane & 3) * 2;
            if (row_a < NN) {
                __half2 h = __floats2half2_rn(c[mi][ni][0] * sa, c[mi][ni][1] * sa);
                *(__half2*)(g_H16a + (long long)row_a * HID + col) = h;
            }
            if (row_b < NN) {
                __half2 h = __floats2half2_rn(c[mi][ni][2] * sb, c[mi][ni][3] * sb);
                *(__half2*)(g_H16a + (long long)row_b * HID + col) = h;
            }
        }
    }
}

// ---------------------------------------------------------------------------
// CSR propagation (fp16 gather, fp32 accumulate): warp per node.
// mode=1: fp16 out = h( dinv*relu(dn*sum + b1) )
// mode=2: fp16 out = h( dn*sum )
// ---------------------------------------------------------------------------
__device__ __forceinline__ void prop_body_h(const __half* __restrict__ in,
                                            __half* __restrict__ outh,
                                            const float* __restrict__ bias,
                                            int mode) {
    int node = (int)((blockIdx.x * (long long)blockDim.x + threadIdx.x) >> 5);
    int lane = threadIdx.x & 31;
    if (node >= NN) return;

    const uint2* IN = (const uint2*)in;
    int beg = g_rowptr[node];
    int end = g_rowptr[node + 1];

    float4 acc = h4_to_f4(IN[(long long)node * 32 + lane]);  // self-loop (pre-scaled)

    int e = beg;
    for (; e + 8 <= end; e += 8) {
        int s0 = g_csr[e];
        int s1 = g_csr[e + 1];
        int s2 = g_csr[e + 2];
        int s3 = g_csr[e + 3];
        int s4 = g_csr[e + 4];
        int s5 = g_csr[e + 5];
        int s6 = g_csr[e + 6];
        int s7 = g_csr[e + 7];
        uint2 u0 = IN[(long long)s0 * 32 + lane];
        uint2 u1 = IN[(long long)s1 * 32 + lane];
        uint2 u2 = IN[(long long)s2 * 32 + lane];
        uint2 u3 = IN[(long long)s3 * 32 + lane];
        uint2 u4 = IN[(long long)s4 * 32 + lane];
        uint2 u5 = IN[(long long)s5 * 32 + lane];
        uint2 u6 = IN[(long long)s6 * 32 + lane];
        uint2 u7 = IN[(long long)s7 * 32 + lane];
        float4 v0 = h4_to_f4(u0), v1 = h4_to_f4(u1), v2 = h4_to_f4(u2), v3 = h4_to_f4(u3);
        float4 v4 = h4_to_f4(u4), v5 = h4_to_f4(u5), v6 = h4_to_f4(u6), v7 = h4_to_f4(u7);
        acc.x += ((v0.x + v1.x) + (v2.x + v3.x)) + ((v4.x + v5.x) + (v6.x + v7.x));
        acc.y += ((v0.y + v1.y) + (v2.y + v3.y)) + ((v4.y + v5.y) + (v6.y + v7.y));
        acc.z += ((v0.z + v1.z) + (v2.z + v3.z)) + ((v4.z + v5.z) + (v6.z + v7.z));
        acc.w += ((v0.w + v1.w) + (v2.w + v3.w)) + ((v4.w + v5.w) + (v6.w + v7.w));
    }
    for (; e + 4 <= end; e += 4) {
        int s0 = g_csr[e];
        int s1 = g_csr[e + 1];
        int s2 = g_csr[e + 2];
        int s3 = g_csr[e + 3];
        float4 v0 = h4_to_f4(IN[(long long)s0 * 32 + lane]);
        float4 v1 = h4_to_f4(IN[(long long)s1 * 32 + lane]);
        float4 v2 = h4_to_f4(IN[(long long)s2 * 32 + lane]);
        float4 v3 = h4_to_f4(IN[(long long)s3 * 32 + lane]);
        acc.x += (v0.x + v1.x) + (v2.x + v3.x);
        acc.y += (v0.y + v1.y) + (v2.y + v3.y);
        acc.z += (v0.z + v1.z) + (v2.z + v3.z);
        acc.w += (v0.w + v1.w) + (v2.w + v3.w);
    }
    for (; e < end; e++) {
        int s = g_csr[e];
        float4 v = h4_to_f4(IN[(long long)s * 32 + lane]);
        acc.x += v.x; acc.y += v.y; acc.z += v.z; acc.w += v.w;
    }

    float dn = g_dinv[node];
    acc.x *= dn; acc.y *= dn; acc.z *= dn; acc.w *= dn;
    if (mode == 1) {
        float4 b = ((const float4*)bias)[lane];
        acc.x = fmaxf(acc.x + b.x, 0.f) * dn;
        acc.y = fmaxf(acc.y + b.y, 0.f) * dn;
        acc.z = fmaxf(acc.z + b.z, 0.f) * dn;
        acc.w = fmaxf(acc.w + b.w, 0.f) * dn;
    }
    ((uint2*)outh)[(long long)node * 32 + lane] = f4_to_h4(acc);
}

__global__ __launch_bounds__(256) void k_prop1(const float* __restrict__ b1) {
    prop_body_h(g_H16a, g_H16b, b1, 1);
}

__global__ __launch_bounds__(256) void k_prop2() {
    prop_body_h(g_H16b, g_H16c, (const float*)0, 2);
}

// ---------------------------------------------------------------------------
// GEMM2 (tensor core): [mu | ls] = g_H16c @ g_W2 + bias  (fp32 out)
// ---------------------------------------------------------------------------
__global__ __launch_bounds__(256) void k_gemm2h(const float* __restrict__ bmu,
                                                const float* __restrict__ bls,
                                                float* __restrict__ out) {
    __shared__ __half As[128 * A_LD];
    __shared__ __half Bs[32 * B_LD];

    int t = threadIdx.x;
    int lane = t & 31;
    int w = t >> 5;
    int wm = w & 3;
    int wn = w >> 2;
    int row0 = blockIdx.x * 128;

    int arow = t >> 1, acol = (t & 1) * 16;
    int brow = t >> 3, bcol = (t & 7) * 16;
    int gr_a = row0 + arow;

    float c[2][8][4];
#pragma unroll
    for (int mi = 0; mi < 2; mi++)
#pragma unroll
        for (int ni = 0; ni < 8; ni++)
#pragma unroll
            for (int q = 0; q < 4; q++) c[mi][ni][q] = 0.f;

    unsigned as_base = (unsigned)__cvta_generic_to_shared(As);
    unsigned bs_base = (unsigned)__cvta_generic_to_shared(Bs);

    for (int k0 = 0; k0 < HID; k0 += 32) {
        {
            uint4 z = make_uint4(0, 0, 0, 0);
            uint4 v0 = z, v1 = z;
            if (gr_a < NN) {
                const uint4* p = (const uint4*)(g_H16c + (long long)gr_a * HID + k0 + acol);
                v0 = p[0];
                v1 = p[1];
            }
            uint4* d = (uint4*)(As + arow * A_LD + acol);
            d[0] = v0;
            d[1] = v1;
        }
        {
            const uint4* p = (const uint4*)(g_W2 + (long long)(k0 + brow) * 128 + bcol);
            uint4* d = (uint4*)(Bs + brow * B_LD + bcol);
            d[0] = p[0];
            d[1] = p[1];
        }
        __syncthreads();

#pragma unroll
        for (int ks = 0; ks < 32; ks += 16) {
            unsigned a[2][4];
#pragma unroll
            for (int mi = 0; mi < 2; mi++) {
                int m = wm * 32 + mi * 16 + (lane & 15);
                unsigned addr = as_base + (m * A_LD + ks + (lane >> 4) * 8) * 2;
                ldsm_x4(a[mi][0], a[mi][1], a[mi][2], a[mi][3], addr);
            }
            unsigned b[8][2];
#pragma unroll
            for (int nb = 0; nb < 4; nb++) {
                int n0 = wn * 64 + nb * 16;
                unsigned addr = bs_base + ((ks + (lane & 15)) * B_LD + n0 + (lane >> 4) * 8) * 2;
                unsigned r0, r1, r2, r3;
                ldsm_x4_t(r0, r1, r2, r3, addr);
                b[2 * nb][0] = r0;     b[2 * nb][1] = r1;
                b[2 * nb + 1][0] = r2; b[2 * nb + 1][1] = r3;
            }
#pragma unroll
            for (int mi = 0; mi < 2; mi++)
#pragma unroll
                for (int ni = 0; ni < 8; ni++)
                    mma16816(c[mi][ni], a[mi], b[ni]);
        }
        __syncthreads();
    }

    // epilogue: wn=0 -> mu (out), wn=1 -> ls (out + NN*OUTC)
    const float* bias = (wn == 0) ? bmu : bls;
    float* base = (wn == 0) ? out : (out + (long long)NN * OUTC);
#pragma unroll
    for (int mi = 0; mi < 2; mi++) {
        int row_a = row0 + wm * 32 + mi * 16 + (lane >> 2);
        int row_b = row_a + 8;
#pragma unroll
        for (int ni = 0; ni < 8; ni++) {
            int cc = ni * 8 + (lane & 3) * 2;   // 0..63 within the half
            float b0 = bias[cc], b1v = bias[cc + 1];
            if (row_a < NN) {
                float2 v = make_float2(c[mi][ni][0] + b0, c[mi][ni][1] + b1v);
                *(float2*)(base + (long long)row_a * OUTC + cc) = v;
            }
            if (row_b < NN) {
                float2 v = make_float2(c[mi][ni][2] + b0, c[mi][ni][3] + b1v);
                *(float2*)(base + (long long)row_b * OUTC + cc) = v;
            }
        }
    }
}

// ---------------------------------------------------------------------------
extern "C" void kernel_launch(void* const* d_in, const int* in_sizes, int n_in,
                              void* d_out, int out_size) {
    const float* x   = (const float*)d_in[0];
    const void*  ei  = d_in[1];
    const float* W1  = (const float*)d_in[2];
    const float* b1  = (const float*)d_in[3];
    const float* Wmu = (const float*)d_in[4];
    const float* bmu = (const float*)d_in[5];
    const float* Wls = (const float*)d_in[6];
    const float* bls = (const float*)d_in[7];
    float* out = (float*)d_out;

    const int E = in_sizes[1] / 2;

    const int nThr    = 256;
    const int nodeBlk = (NN + nThr - 1) / nThr;
    const int edgeBlk = (E + nThr - 1) / nThr;
    const int scanBlk = (NN + 1023) / 1024;   // 98
    const int propBlk = (int)(((long long)NN * 32 + nThr - 1) / nThr);
    const int gemmBlk = (NN + 127) / 128;
    const int cvtWBlk = (INCH * HID / 4 + nThr - 1) / nThr;
    const int cvtW2Blk = (HID * 128 + nThr - 1) / nThr;

    // One-time side-stream/event setup (host-side resources only; created on
    // the first, uncaptured correctness call; identical GPU work every call).
    static cudaStream_t sB = 0;
    static cudaEvent_t evFork = 0, evDinv = 0, evJoin = 0;
    if (sB == 0) {
        cudaStreamCreateWithFlags(&sB, cudaStreamNonBlocking);
        cudaEventCreateWithFlags(&evFork, cudaEventDisableTiming);
        cudaEventCreateWithFlags(&evDinv, cudaEventDisableTiming);
        cudaEventCreateWithFlags(&evJoin, cudaEventDisableTiming);
    }

    // ---- fork: side stream does weight conversions immediately ----
    cudaEventRecord(evFork, 0);
    cudaStreamWaitEvent(sB, evFork, 0);
    k_cvtW<<<cvtWBlk, nThr, 0, sB>>>(W1);
    k_cvtW2<<<cvtW2Blk, nThr, 0, sB>>>(Wmu, Wls);

    // ---- main stream: CSR build ----
    k_detect<<<1, 256>>>((const int*)ei);
    k_zero_deg<<<nodeBlk, nThr>>>();
    k_deg<<<edgeBlk, nThr>>>(ei, E);
    k_scan_block<<<scanBlk, 1024>>>(NN);
    k_scan_top<<<1, 32>>>(scanBlk);
    k_finalize<<<nodeBlk, nThr>>>(NN, E);
    cudaEventRecord(evDinv, 0);          // dinv ready for gemm1h epilogue

    // side stream: gemm1h overlaps with scatter on the main stream
    cudaStreamWaitEvent(sB, evDinv, 0);
    k_gemm1h<<<gemmBlk, nThr, 0, sB>>>(x);
    cudaEventRecord(evJoin, sB);

    k_scatter<<<edgeBlk, nThr>>>(ei, E);

    // ---- join: prop chain needs CSR (main) + g_H16a (side) ----
    cudaStreamWaitEvent(0, evJoin, 0);
    k_prop1<<<propBlk, nThr>>>(b1);
    k_prop2<<<propBlk, nThr>>>();
    k_gemm2h<<<gemmBlk, nThr>>>(bmu, bls, out);
}